// round 7
// baseline (speedup 1.0000x reference)
#include <cuda_runtime.h>
#include <cuda_bf16.h>
#include <cstdint>

#define NN 50000
#define NPAD 50048          // 391 * 128
#define NE 800000
#define DD 256
#define LAT 128

// ---------------- scratch (static __device__ globals; no allocs) ----------
static __device__ int   g_is64;
static __device__ int   g_deg[NN];
static __device__ float g_dinv[NN];
static __device__ int   g_rowstart[NN + 1];
static __device__ int   g_pos[NN];
static __device__ int   g_csrc[NE];
static __device__ float g_cnrm[NE];
static __device__ __align__(16) float         g_z [(size_t)NN * DD];
static __device__ __align__(16) __nv_bfloat16 g_wt1_0[DD * DD];   // W1^T hi [N,K]
static __device__ __align__(16) __nv_bfloat16 g_wt1_1[DD * DD];
static __device__ __align__(16) __nv_bfloat16 g_wtc_0[DD * DD];   // [Wmu|Wlv]^T hi
static __device__ __align__(16) __nv_bfloat16 g_wtc_1[DD * DD];
static __device__ float g_bcat[DD];

// ---------------- helpers ---------------------------------------------------
__device__ __forceinline__ uint32_t smem_u32(const void* p) {
    uint32_t a;
    asm("{ .reg .u64 t; cvta.to.shared.u64 t, %1; cvt.u32.u64 %0, t; }"
        : "=r"(a) : "l"(p));
    return a;
}

__device__ __forceinline__ int load_idx(const void* ei, int pos) {
    if (g_is64) return (int)((const long long*)ei)[pos];
    return ((const int*)ei)[pos];
}

// ---------------- k1: zero deg + weight prep + parallel detect -------------
__global__ void prep_kernel(const void* __restrict__ ei,
                            const float* __restrict__ W1,
                            const float* __restrict__ Wmu,
                            const float* __restrict__ Wlv,
                            const float* __restrict__ bmu,
                            const float* __restrict__ blv) {
    int idx = blockIdx.x * 256 + threadIdx.x;      // 0..65535
    if (idx < NN) g_deg[idx] = 0;

    int n = idx >> 8, k = idx & 255;
    float v1 = W1[k * DD + n];
    __nv_bfloat16 h = __float2bfloat16(v1);
    g_wt1_0[idx] = h;
    g_wt1_1[idx] = __float2bfloat16(v1 - __bfloat162float(h));
    float v2 = (n < LAT) ? Wmu[k * LAT + n] : Wlv[k * LAT + (n - LAT)];
    h = __float2bfloat16(v2);
    g_wtc_0[idx] = h;
    g_wtc_1[idx] = __float2bfloat16(v2 - __bfloat162float(h));
    if (idx < DD) g_bcat[idx] = (idx < LAT) ? bmu[idx] : blv[idx - LAT];

    if (blockIdx.x == 0) {      // parallel int64-vs-int32 detection
        long long v = ((const long long*)ei)[threadIdx.x];
        int ok = (v >= 0 && v < NN) ? 1 : 0;
        int all = __syncthreads_and(ok);
        if (threadIdx.x == 0) g_is64 = all;
    }
}

// ---------------- k2: degree count -----------------------------------------
__global__ void count_deg_kernel(const void* __restrict__ ei) {
    int e = blockIdx.x * blockDim.x + threadIdx.x;
    if (e < NE) atomicAdd(&g_deg[load_idx(ei, NE + e)], 1);
}

// ---------------- k3: single-block scan + dinv ------------------------------
__global__ void __launch_bounds__(1024) scan_kernel() {
    __shared__ int sh[1024];
    const int CH = 49;                 // 1024*49 = 50176 >= NN
    int t = threadIdx.x;
    int base = t * CH;
    int sum = 0;
    for (int k = 0; k < CH; k++) {
        int i = base + k;
        if (i < NN) sum += g_deg[i];
    }
    sh[t] = sum;
    __syncthreads();
    for (int o = 1; o < 1024; o <<= 1) {
        int x = (t >= o) ? sh[t - o] : 0;
        __syncthreads();
        sh[t] += x;
        __syncthreads();
    }
    int running = sh[t] - sum;         // exclusive prefix
    for (int k = 0; k < CH; k++) {
        int i = base + k;
        if (i < NN) {
            int d = g_deg[i];
            g_rowstart[i] = running;
            g_pos[i] = running;
            g_dinv[i] = rsqrtf((float)d + 1.0f);
            running += d;
        }
    }
    if (t == 1023) g_rowstart[NN] = running;
}

// ---------------- k4: CSR fill ----------------------------------------------
__global__ void csr_fill_kernel(const void* __restrict__ ei) {
    int e = blockIdx.x * blockDim.x + threadIdx.x;
    if (e < NE) {
        int s = load_idx(ei, e);
        int d = load_idx(ei, NE + e);
        int slot = atomicAdd(&g_pos[d], 1);
        g_csrc[slot] = s;
        g_cnrm[slot] = g_dinv[s] * g_dinv[d];
    }
}

// ---------------- fused agg + mma.sync GEMM ---------------------------------
// Per CTA: aggregate 128 rows (CSR gather, fp32 in regs) -> bf16 hi/lo planes
// in smem -> full 128x256x256 GEMM (3-product split) from resident A with
// double-buffered B. EPI 1: z = relu(.+b). EPI 2: split cols to mu / logvar.
//
// smem: A0 [128 x 528B] @0, A1 @67584, B stages @135168 (2 st x 2 pl x 256x80B)
#define SB_A0   0
#define SB_A1   67584
#define SB_B    135168
#define SMEM_F  217088

__device__ __forceinline__ void ldmx4(uint32_t* r, uint32_t addr) {
    asm volatile("ldmatrix.sync.aligned.m8n8.x4.shared.b16 {%0,%1,%2,%3}, [%4];"
                 : "=r"(r[0]), "=r"(r[1]), "=r"(r[2]), "=r"(r[3]) : "r"(addr));
}
__device__ __forceinline__ void ldmx2(uint32_t* r, uint32_t addr) {
    asm volatile("ldmatrix.sync.aligned.m8n8.x2.shared.b16 {%0,%1}, [%2];"
                 : "=r"(r[0]), "=r"(r[1]) : "r"(addr));
}
__device__ __forceinline__ void mma16816(float* c, const uint32_t* a,
                                         const uint32_t* b) {
    asm volatile(
        "mma.sync.aligned.m16n8k16.row.col.f32.bf16.bf16.f32 "
        "{%0,%1,%2,%3}, {%4,%5,%6,%7}, {%8,%9}, {%0,%1,%2,%3};"
        : "+f"(c[0]), "+f"(c[1]), "+f"(c[2]), "+f"(c[3])
        : "r"(a[0]), "r"(a[1]), "r"(a[2]), "r"(a[3]), "r"(b[0]), "r"(b[1]));
}

template <int EPI>
__global__ void __launch_bounds__(256, 1) fused_kernel(
        const float4* __restrict__ feat,
        const __nv_bfloat16* __restrict__ B0, const __nv_bfloat16* __restrict__ B1,
        const float* __restrict__ bias,
        float* __restrict__ out0, float* __restrict__ out1) {
    extern __shared__ char smem[];
    uint32_t sb = smem_u32(smem);
    int tid = threadIdx.x;
    int lane = tid & 31, w = tid >> 5;
    int warp_m = w & 3, warp_n = w >> 2;
    int row0 = blockIdx.x * 128;

    // B chunk loader: chunk c (k in [32c,32c+32)) -> stage st, both planes
    auto load_B = [&](int st, int c) {
        #pragma unroll
        for (int it = 0; it < 8; it++) {
            int i   = tid + it * 256;          // 0..2047
            int u   = i & 3;                   // 16B unit within 64B
            int row = (i >> 2) & 255;          // n index
            int p   = i >> 10;                 // plane
            const void* src = (p ? B1 : B0) + (size_t)row * DD + c * 32 + u * 8;
            uint32_t dst = sb + SB_B + st * 40960 + p * 20480 + row * 80 + u * 16;
            asm volatile("cp.async.cg.shared.global [%0], [%1], 16;"
                         :: "r"(dst), "l"(src));
        }
        asm volatile("cp.async.commit_group;" ::: "memory");
    };

    load_B(0, 0);   // prefetch first B chunk; overlaps the gather phase

    // ---- phase 1: aggregate 128 rows into A planes (bf16 hi/lo) ----
    {
        int j  = tid & 63;                     // float4 lane (16B)
        int rg = tid >> 6;                     // 0..3
        for (int g = 0; g < 32; g++) {
            int lr = g * 4 + rg;
            int gr = row0 + lr;
            float4 acc = make_float4(0.f, 0.f, 0.f, 0.f);
            if (gr < NN) {
                int beg = g_rowstart[gr];
                int end = g_rowstart[gr + 1];
                float d  = g_dinv[gr];
                float d2 = d * d;
                float4 v = feat[(size_t)gr * 64 + j];
                acc.x = v.x * d2; acc.y = v.y * d2;
                acc.z = v.z * d2; acc.w = v.w * d2;
                int e = beg;
                for (; e + 1 < end; e += 2) {
                    int   s0 = g_csrc[e],  s1 = g_csrc[e + 1];
                    float n0 = g_cnrm[e],  n1 = g_cnrm[e + 1];
                    float4 u0 = feat[(size_t)s0 * 64 + j];
                    float4 u1 = feat[(size_t)s1 * 64 + j];
                    acc.x += n0 * u0.x + n1 * u1.x;
                    acc.y += n0 * u0.y + n1 * u1.y;
                    acc.z += n0 * u0.z + n1 * u1.z;
                    acc.w += n0 * u0.w + n1 * u1.w;
                }
                if (e < end) {
                    int   s0 = g_csrc[e];
                    float n0 = g_cnrm[e];
                    float4 u0 = feat[(size_t)s0 * 64 + j];
                    acc.x += n0 * u0.x; acc.y += n0 * u0.y;
                    acc.z += n0 * u0.z; acc.w += n0 * u0.w;
                }
            }
            __nv_bfloat16 h[4], l[4];
            float vv[4] = {acc.x, acc.y, acc.z, acc.w};
            #pragma unroll
            for (int q = 0; q < 4; q++) {
                h[q] = __float2bfloat16(vv[q]);
                l[q] = __float2bfloat16(vv[q] - __bfloat162float(h[q]));
            }
            *(uint2*)(smem + SB_A0 + lr * 528 + 8 * j) = *(uint2*)h;
            *(uint2*)(smem + SB_A1 + lr * 528 + 8 * j) = *(uint2*)l;
        }
    }
    asm volatile("cp.async.wait_group 0;" ::: "memory");
    __syncthreads();    // A planes + B chunk 0 visible

    // ---- phase 2: GEMM from resident A ----
    float acc[2][16][4];
    #pragma unroll
    for (int i = 0; i < 2; i++)
        #pragma unroll
        for (int j = 0; j < 16; j++)
            #pragma unroll
            for (int q = 0; q < 4; q++) acc[i][j][q] = 0.0f;

    int ar = 32 * warp_m + (lane & 15);
    int ac = (lane >> 4) << 3;
    int br = 128 * warp_n + (lane & 7);
    int bc = ((lane >> 3) & 1) << 3;

    for (int c = 0; c < 8; c++) {
        int st = c & 1;
        if (c < 7) load_B(st ^ 1, c + 1);
        uint32_t sB0 = sb + SB_B + st * 40960;
        uint32_t sB1 = sB0 + 20480;

        #pragma unroll
        for (int s = 0; s < 2; s++) {
            uint32_t a0f[2][4], a1f[2][4];
            #pragma unroll
            for (int i = 0; i < 2; i++) {
                uint32_t off = (uint32_t)(ar + 16 * i) * 528
                             + (uint32_t)(ac + 16 * s + 32 * c) * 2;
                ldmx4(a0f[i], sb + SB_A0 + off);
                ldmx4(a1f[i], sb + SB_A1 + off);
            }
            #pragma unroll
            for (int j = 0; j < 16; j++) {
                uint32_t b0f[2], b1f[2];
                uint32_t off = (uint32_t)(br + 8 * j) * 80
                             + (uint32_t)(bc + 16 * s) * 2;
                ldmx2(b0f, sB0 + off);
                ldmx2(b1f, sB1 + off);
                #pragma unroll
                for (int i = 0; i < 2; i++) {
                    mma16816(acc[i][j], a0f[i], b0f);
                    mma16816(acc[i][j], a0f[i], b1f);
                    mma16816(acc[i][j], a1f[i], b0f);
                }
            }
        }
        asm volatile("cp.async.wait_group 0;" ::: "memory");
        __syncthreads();
    }

    // ---- epilogue ----
    #pragma unroll
    for (int i = 0; i < 2; i++) {
        int r = row0 + 32 * warp_m + 16 * i + (lane >> 2);
        #pragma unroll
        for (int j = 0; j < 16; j++) {
            int cg = 128 * warp_n + 8 * j + ((lane & 3) << 1);
            float b0v = bias[cg], b1v = bias[cg + 1];
            float v0 = acc[i][j][0] + b0v, v1 = acc[i][j][1] + b1v;
            float v2 = acc[i][j][2] + b0v, v3 = acc[i][j][3] + b1v;
            if (EPI == 1) {
                v0 = fmaxf(v0, 0.0f); v1 = fmaxf(v1, 0.0f);
                v2 = fmaxf(v2, 0.0f); v3 = fmaxf(v3, 0.0f);
                if (r < NN)
                    *(float2*)(out0 + (size_t)r * DD + cg) = make_float2(v0, v1);
                if (r + 8 < NN)
                    *(float2*)(out0 + (size_t)(r + 8) * DD + cg) = make_float2(v2, v3);
            } else {
                float* o  = (cg < LAT) ? out0 + (size_t)r * LAT + cg
                                       : out1 + (size_t)r * LAT + (cg - LAT);
                float* o8 = (cg < LAT) ? out0 + (size_t)(r + 8) * LAT + cg
                                       : out1 + (size_t)(r + 8) * LAT + (cg - LAT);
                if (r < NN)     *(float2*)o  = make_float2(v0, v1);
                if (r + 8 < NN) *(float2*)o8 = make_float2(v2, v3);
            }
        }
    }
}

// ---------------- launch ---------------------------------------------------
extern "C" void kernel_launch(void* const* d_in, const int* in_sizes, int n_in,
                              void* d_out, int out_size) {
    const float* x    = (const float*)d_in[0];
    const void*  ei   = d_in[1];
    const float* W1   = (const float*)d_in[2];
    const float* b1   = (const float*)d_in[3];
    const float* Wmu  = (const float*)d_in[4];
    const float* bmu  = (const float*)d_in[5];
    const float* Wlv  = (const float*)d_in[6];
    const float* blv  = (const float*)d_in[7];
    float* out_mu = (float*)d_out;
    float* out_lv = (float*)d_out + (size_t)NN * LAT;

    float* z = nullptr;
    __nv_bfloat16 *wt10 = nullptr, *wt11 = nullptr, *wtc0 = nullptr, *wtc1 = nullptr;
    float* bcat = nullptr;
    cudaGetSymbolAddress((void**)&z,    g_z);
    cudaGetSymbolAddress((void**)&wt10, g_wt1_0);
    cudaGetSymbolAddress((void**)&wt11, g_wt1_1);
    cudaGetSymbolAddress((void**)&wtc0, g_wtc_0);
    cudaGetSymbolAddress((void**)&wtc1, g_wtc_1);
    cudaGetSymbolAddress((void**)&bcat, g_bcat);
    (void)n_in; (void)in_sizes; (void)out_size;

    cudaFuncSetAttribute(fused_kernel<1>,
                         cudaFuncAttributeMaxDynamicSharedMemorySize, SMEM_F);
    cudaFuncSetAttribute(fused_kernel<2>,
                         cudaFuncAttributeMaxDynamicSharedMemorySize, SMEM_F);

    // ---- graph prep (4 kernels) ----
    prep_kernel<<<256, 256>>>(ei, W1, Wmu, Wlv, bmu, blv);
    count_deg_kernel<<<(NE + 255) / 256, 256>>>(ei);
    scan_kernel<<<1, 1024>>>();
    csr_fill_kernel<<<(NE + 255) / 256, 256>>>(ei);

    // ---- layer 1: fused agg(x) + GEMM(W1) -> z (relu) ----
    fused_kernel<1><<<NPAD / 128, 256, SMEM_F>>>((const float4*)x, wt10, wt11,
                                                 b1, z, nullptr);

    // ---- layers 2/3: fused agg(z) + GEMM([Wmu|Wlv]) -> mu, logvar ----
    fused_kernel<2><<<NPAD / 128, 256, SMEM_F>>>((const float4*)z, wtc0, wtc1,
                                                 bcat, out_mu, out_lv);
}

// round 8
// speedup vs baseline: 1.6402x; 1.6402x over previous
#include <cuda_runtime.h>
#include <cuda_bf16.h>
#include <cstdint>

#define NN 50000
#define NPAD 50048          // 391 * 128
#define NE 800000
#define DD 256
#define LAT 128

// ---------------- scratch (static __device__ globals; no allocs) ----------
static __device__ int   g_is64;
static __device__ int   g_deg[NN];
static __device__ float g_dinv[NN];
static __device__ int   g_rowstart[NN + 1];
static __device__ int   g_pos[NN];
static __device__ int   g_csrc[NE];
static __device__ float g_cnrm[NE];
static __device__ __align__(16) float         g_z [(size_t)NN * DD];
static __device__ __align__(16) __nv_bfloat16 g_a0[(size_t)NPAD * DD];   // A hi plane
static __device__ __align__(16) __nv_bfloat16 g_a1[(size_t)NPAD * DD];   // A lo plane
static __device__ __align__(16) __nv_bfloat16 g_wt1_0[DD * DD];   // W1^T hi [N,K]
static __device__ __align__(16) __nv_bfloat16 g_wt1_1[DD * DD];
static __device__ __align__(16) __nv_bfloat16 g_wtc_0[DD * DD];   // [Wmu|Wlv]^T hi
static __device__ __align__(16) __nv_bfloat16 g_wtc_1[DD * DD];
static __device__ float g_bcat[DD];

// ---------------- helpers ---------------------------------------------------
__device__ __forceinline__ uint32_t smem_u32(const void* p) {
    uint32_t a;
    asm("{ .reg .u64 t; cvta.to.shared.u64 t, %1; cvt.u32.u64 %0, t; }"
        : "=r"(a) : "l"(p));
    return a;
}

__device__ __forceinline__ int load_idx(const void* ei, int pos) {
    if (g_is64) return (int)((const long long*)ei)[pos];
    return ((const int*)ei)[pos];
}

// ---------------- k1: zero deg + weight prep + parallel detect -------------
__global__ void prep_kernel(const void* __restrict__ ei,
                            const float* __restrict__ W1,
                            const float* __restrict__ Wmu,
                            const float* __restrict__ Wlv,
                            const float* __restrict__ bmu,
                            const float* __restrict__ blv) {
    int idx = blockIdx.x * 256 + threadIdx.x;      // 0..65535
    if (idx < NN) g_deg[idx] = 0;

    int n = idx >> 8, k = idx & 255;
    float v1 = W1[k * DD + n];
    __nv_bfloat16 h = __float2bfloat16(v1);
    g_wt1_0[idx] = h;
    g_wt1_1[idx] = __float2bfloat16(v1 - __bfloat162float(h));
    float v2 = (n < LAT) ? Wmu[k * LAT + n] : Wlv[k * LAT + (n - LAT)];
    h = __float2bfloat16(v2);
    g_wtc_0[idx] = h;
    g_wtc_1[idx] = __float2bfloat16(v2 - __bfloat162float(h));
    if (idx < DD) g_bcat[idx] = (idx < LAT) ? bmu[idx] : blv[idx - LAT];

    if (blockIdx.x == 0) {      // parallel int64-vs-int32 detection
        long long v = ((const long long*)ei)[threadIdx.x];
        int ok = (v >= 0 && v < NN) ? 1 : 0;
        int all = __syncthreads_and(ok);
        if (threadIdx.x == 0) g_is64 = all;
    }
}

// ---------------- k2: degree count -----------------------------------------
__global__ void count_deg_kernel(const void* __restrict__ ei) {
    int e = blockIdx.x * blockDim.x + threadIdx.x;
    if (e < NE) atomicAdd(&g_deg[load_idx(ei, NE + e)], 1);
}

// ---------------- k3: single-block scan + dinv ------------------------------
__global__ void __launch_bounds__(1024) scan_kernel() {
    __shared__ int sh[1024];
    const int CH = 49;                 // 1024*49 = 50176 >= NN
    int t = threadIdx.x;
    int base = t * CH;
    int sum = 0;
    for (int k = 0; k < CH; k++) {
        int i = base + k;
        if (i < NN) sum += g_deg[i];
    }
    sh[t] = sum;
    __syncthreads();
    for (int o = 1; o < 1024; o <<= 1) {
        int x = (t >= o) ? sh[t - o] : 0;
        __syncthreads();
        sh[t] += x;
        __syncthreads();
    }
    int running = sh[t] - sum;         // exclusive prefix
    for (int k = 0; k < CH; k++) {
        int i = base + k;
        if (i < NN) {
            int d = g_deg[i];
            g_rowstart[i] = running;
            g_pos[i] = running;
            g_dinv[i] = rsqrtf((float)d + 1.0f);
            running += d;
        }
    }
    if (t == 1023) g_rowstart[NN] = running;
}

// ---------------- k4: CSR fill ----------------------------------------------
__global__ void csr_fill_kernel(const void* __restrict__ ei) {
    int e = blockIdx.x * blockDim.x + threadIdx.x;
    if (e < NE) {
        int s = load_idx(ei, e);
        int d = load_idx(ei, NE + e);
        int slot = atomicAdd(&g_pos[d], 1);
        g_csrc[slot] = s;
        g_cnrm[slot] = g_dinv[s] * g_dinv[d];
    }
}

// ---------------- CSR aggregation -> split bf16 planes ---------------------
__global__ void __launch_bounds__(256) agg_kernel(
        const float4* __restrict__ feat,
        __nv_bfloat16* __restrict__ p0, __nv_bfloat16* __restrict__ p1) {
    int gid = (blockIdx.x * blockDim.x + threadIdx.x) >> 6;
    int j   = threadIdx.x & 63;
    if (gid >= NN) return;

    int beg = g_rowstart[gid];
    int end = g_rowstart[gid + 1];
    float d  = g_dinv[gid];
    float d2 = d * d;

    float4 v = feat[(size_t)gid * 64 + j];
    float4 acc = make_float4(v.x * d2, v.y * d2, v.z * d2, v.w * d2);

    int e = beg;
    for (; e + 3 < end; e += 4) {               // 4-wide: more loads in flight
        int   s0 = g_csrc[e],     s1 = g_csrc[e + 1];
        int   s2 = g_csrc[e + 2], s3 = g_csrc[e + 3];
        float n0 = g_cnrm[e],     n1 = g_cnrm[e + 1];
        float n2 = g_cnrm[e + 2], n3 = g_cnrm[e + 3];
        float4 u0 = feat[(size_t)s0 * 64 + j];
        float4 u1 = feat[(size_t)s1 * 64 + j];
        float4 u2 = feat[(size_t)s2 * 64 + j];
        float4 u3 = feat[(size_t)s3 * 64 + j];
        acc.x += n0 * u0.x + n1 * u1.x + n2 * u2.x + n3 * u3.x;
        acc.y += n0 * u0.y + n1 * u1.y + n2 * u2.y + n3 * u3.y;
        acc.z += n0 * u0.z + n1 * u1.z + n2 * u2.z + n3 * u3.z;
        acc.w += n0 * u0.w + n1 * u1.w + n2 * u2.w + n3 * u3.w;
    }
    for (; e < end; e++) {
        int   s0 = g_csrc[e];
        float n0 = g_cnrm[e];
        float4 u0 = feat[(size_t)s0 * 64 + j];
        acc.x += n0 * u0.x;
        acc.y += n0 * u0.y;
        acc.z += n0 * u0.z;
        acc.w += n0 * u0.w;
    }

    __nv_bfloat16 h[4], l[4];
    float vv[4] = {acc.x, acc.y, acc.z, acc.w};
    #pragma unroll
    for (int i = 0; i < 4; i++) {
        h[i] = __float2bfloat16(vv[i]);
        l[i] = __float2bfloat16(vv[i] - __bfloat162float(h[i]));
    }
    size_t off = (size_t)gid * DD + 4 * j;
    *(uint2*)(p0 + off) = *(uint2*)h;
    *(uint2*)(p1 + off) = *(uint2*)l;
}

// ---------------- mma.sync bf16 GEMM ---------------------------------------
// C[M,256] = (A0+A1) @ (B0+B1)^T  (B stored [N,K], K-contiguous)
// 3-product split: a0b0 + a0b1 + a1b0, fp32 accumulators.
// BM=128, BN=128, BK=32, 8 warps (warp tile 32x64), cp.async double buffer.
#define SMEM_ARR   10240                 // 128 rows * 80 B
#define SMEM_STAGE (4 * SMEM_ARR)        // A0,A1,B0,B1
#define SMEM_TOT_G (2 * SMEM_STAGE)      // 81920 B

__device__ __forceinline__ void ldmx4(uint32_t* r, uint32_t addr) {
    asm volatile("ldmatrix.sync.aligned.m8n8.x4.shared.b16 {%0,%1,%2,%3}, [%4];"
                 : "=r"(r[0]), "=r"(r[1]), "=r"(r[2]), "=r"(r[3]) : "r"(addr));
}
__device__ __forceinline__ void ldmx2(uint32_t* r, uint32_t addr) {
    asm volatile("ldmatrix.sync.aligned.m8n8.x2.shared.b16 {%0,%1}, [%2];"
                 : "=r"(r[0]), "=r"(r[1]) : "r"(addr));
}
__device__ __forceinline__ void mma16816(float* c, const uint32_t* a,
                                         const uint32_t* b) {
    asm volatile(
        "mma.sync.aligned.m16n8k16.row.col.f32.bf16.bf16.f32 "
        "{%0,%1,%2,%3}, {%4,%5,%6,%7}, {%8,%9}, {%0,%1,%2,%3};"
        : "+f"(c[0]), "+f"(c[1]), "+f"(c[2]), "+f"(c[3])
        : "r"(a[0]), "r"(a[1]), "r"(a[2]), "r"(a[3]), "r"(b[0]), "r"(b[1]));
}

template <int EPI>
__global__ void __launch_bounds__(256) gemm_mma_kernel(
        const __nv_bfloat16* __restrict__ A0, const __nv_bfloat16* __restrict__ A1,
        const __nv_bfloat16* __restrict__ B0, const __nv_bfloat16* __restrict__ B1,
        const float* __restrict__ bias,
        float* __restrict__ out0, float* __restrict__ out1) {
    extern __shared__ char smem[];
    uint32_t sb = smem_u32(smem);
    int tid = threadIdx.x;
    int lane = tid & 31, w = tid >> 5;
    int warp_m = w & 3, warp_n = w >> 2;
    int row0 = blockIdx.x * 128;
    int col0 = blockIdx.y * 128;

    auto load_chunk = [&](int st, int c) {
        #pragma unroll
        for (int it = 0; it < 8; it++) {
            int i   = tid + it * 256;
            int u   = i & 3;                 // 16B unit within 64B row-chunk
            int row = (i >> 2) & 127;
            int arr = i >> 9;                // 0:A0 1:A1 2:B0 3:B1
            const __nv_bfloat16* base = (arr == 0) ? A0 : (arr == 1) ? A1
                                      : (arr == 2) ? B0 : B1;
            int grow = (arr < 2) ? (row0 + row) : (col0 + row);
            const void* src = base + (size_t)grow * DD + c * 32 + u * 8;
            uint32_t dst = sb + st * SMEM_STAGE + arr * SMEM_ARR + row * 80 + u * 16;
            asm volatile("cp.async.cg.shared.global [%0], [%1], 16;"
                         :: "r"(dst), "l"(src));
        }
        asm volatile("cp.async.commit_group;" ::: "memory");
    };

    float acc[2][8][4];
    #pragma unroll
    for (int i = 0; i < 2; i++)
        #pragma unroll
        for (int j = 0; j < 8; j++)
            #pragma unroll
            for (int q = 0; q < 4; q++) acc[i][j][q] = 0.0f;

    load_chunk(0, 0);
    asm volatile("cp.async.wait_group 0;" ::: "memory");
    __syncthreads();

    int ar = 32 * warp_m + (lane & 15);
    int ac = (lane >> 4) << 3;
    int br = 64 * warp_n + (lane & 7);
    int bc = ((lane >> 3) & 1) << 3;

    for (int c = 0; c < 8; c++) {
        int st = c & 1;
        if (c < 7) load_chunk(st ^ 1, c + 1);

        uint32_t sA0 = sb + st * SMEM_STAGE;
        uint32_t sA1 = sA0 + SMEM_ARR;
        uint32_t sB0 = sA0 + 2 * SMEM_ARR;
        uint32_t sB1 = sA0 + 3 * SMEM_ARR;

        #pragma unroll
        for (int s = 0; s < 2; s++) {
            uint32_t a0f[2][4], a1f[2][4];
            #pragma unroll
            for (int i = 0; i < 2; i++) {
                uint32_t off = (uint32_t)(ar + 16 * i) * 80 + (ac + 16 * s) * 2;
                ldmx4(a0f[i], sA0 + off);
                ldmx4(a1f[i], sA1 + off);
            }
            #pragma unroll
            for (int j = 0; j < 8; j++) {
                uint32_t b0f[2], b1f[2];
                uint32_t off = (uint32_t)(br + 8 * j) * 80 + (bc + 16 * s) * 2;
                ldmx2(b0f, sB0 + off);
                ldmx2(b1f, sB1 + off);
                #pragma unroll
                for (int i = 0; i < 2; i++) {
                    mma16816(acc[i][j], a0f[i], b0f);
                    mma16816(acc[i][j], a0f[i], b1f);
                    mma16816(acc[i][j], a1f[i], b0f);
                }
            }
        }
        asm volatile("cp.async.wait_group 0;" ::: "memory");
        __syncthreads();
    }

    // ---- epilogue ----
    #pragma unroll
    for (int i = 0; i < 2; i++) {
        int r = row0 + 32 * warp_m + 16 * i + (lane >> 2);
        #pragma unroll
        for (int j = 0; j < 8; j++) {
            int cg = col0 + 64 * warp_n + 8 * j + ((lane & 3) << 1);
            float b0v = bias[cg], b1v = bias[cg + 1];
            float v0 = acc[i][j][0] + b0v, v1 = acc[i][j][1] + b1v;
            float v2 = acc[i][j][2] + b0v, v3 = acc[i][j][3] + b1v;
            if (EPI == 1) {
                v0 = fmaxf(v0, 0.0f); v1 = fmaxf(v1, 0.0f);
                v2 = fmaxf(v2, 0.0f); v3 = fmaxf(v3, 0.0f);
                if (r < NN)
                    *(float2*)(out0 + (size_t)r * DD + cg) = make_float2(v0, v1);
                if (r + 8 < NN)
                    *(float2*)(out0 + (size_t)(r + 8) * DD + cg) = make_float2(v2, v3);
            } else {
                float* o  = (cg < LAT) ? out0 + (size_t)r * LAT + cg
                                       : out1 + (size_t)r * LAT + (cg - LAT);
                float* o8 = (cg < LAT) ? out0 + (size_t)(r + 8) * LAT + cg
                                       : out1 + (size_t)(r + 8) * LAT + (cg - LAT);
                if (r < NN)     *(float2*)o  = make_float2(v0, v1);
                if (r + 8 < NN) *(float2*)o8 = make_float2(v2, v3);
            }
        }
    }
}

// ---------------- launch ---------------------------------------------------
extern "C" void kernel_launch(void* const* d_in, const int* in_sizes, int n_in,
                              void* d_out, int out_size) {
    const float* x    = (const float*)d_in[0];
    const void*  ei   = d_in[1];
    const float* W1   = (const float*)d_in[2];
    const float* b1   = (const float*)d_in[3];
    const float* Wmu  = (const float*)d_in[4];
    const float* bmu  = (const float*)d_in[5];
    const float* Wlv  = (const float*)d_in[6];
    const float* blv  = (const float*)d_in[7];
    float* out_mu = (float*)d_out;
    float* out_lv = (float*)d_out + (size_t)NN * LAT;

    float* z = nullptr;
    __nv_bfloat16 *a0 = nullptr, *a1 = nullptr;
    __nv_bfloat16 *wt10 = nullptr, *wt11 = nullptr, *wtc0 = nullptr, *wtc1 = nullptr;
    float* bcat = nullptr;
    cudaGetSymbolAddress((void**)&z,    g_z);
    cudaGetSymbolAddress((void**)&a0,   g_a0);
    cudaGetSymbolAddress((void**)&a1,   g_a1);
    cudaGetSymbolAddress((void**)&wt10, g_wt1_0);
    cudaGetSymbolAddress((void**)&wt11, g_wt1_1);
    cudaGetSymbolAddress((void**)&wtc0, g_wtc_0);
    cudaGetSymbolAddress((void**)&wtc1, g_wtc_1);
    cudaGetSymbolAddress((void**)&bcat, g_bcat);
    (void)n_in; (void)in_sizes; (void)out_size;

    cudaFuncSetAttribute(gemm_mma_kernel<1>,
                         cudaFuncAttributeMaxDynamicSharedMemorySize, SMEM_TOT_G);
    cudaFuncSetAttribute(gemm_mma_kernel<2>,
                         cudaFuncAttributeMaxDynamicSharedMemorySize, SMEM_TOT_G);

    // ---- graph prep (4 kernels) ----
    prep_kernel<<<256, 256>>>(ei, W1, Wmu, Wlv, bmu, blv);
    count_deg_kernel<<<(NE + 255) / 256, 256>>>(ei);
    scan_kernel<<<1, 1024>>>();
    csr_fill_kernel<<<(NE + 255) / 256, 256>>>(ei);

    // ---- layer 1 ----
    agg_kernel<<<(NN * 64 + 255) / 256, 256>>>((const float4*)x, a0, a1);
    gemm_mma_kernel<1><<<dim3(NPAD / 128, 2), 256, SMEM_TOT_G>>>(a0, a1, wt10, wt11,
                                                                 b1, z, nullptr);

    // ---- layers 2/3 (shared aggregation, fused N=256 GEMM) ----
    agg_kernel<<<(NN * 64 + 255) / 256, 256>>>((const float4*)z, a0, a1);
    gemm_mma_kernel<2><<<dim3(NPAD / 128, 2), 256, SMEM_TOT_G>>>(a0, a1, wtc0, wtc1,
                                                                 bcat, out_mu, out_lv);
}

// round 10
// speedup vs baseline: 2.1595x; 1.3166x over previous
#include <cuda_runtime.h>
#include <cuda_bf16.h>
#include <cstdint>

#define NN 50000
#define NPAD 50048          // 391 * 128
#define NE 800000
#define DD 256
#define LAT 128
#define NBLK 196            // ceil(NN/256)

// ---------------- scratch (static __device__ globals; no allocs) ----------
static __device__ int   g_is64;
static __device__ int   g_deg[NN];
static __device__ float g_dinv[NN];
static __device__ int   g_rowstart[NN + 1];
static __device__ int   g_pos[NN];
static __device__ int   g_bsum[256];
static __device__ int   g_boff[256];
static __device__ int   g_csrc[NE];
static __device__ float g_cnrm[NE];
static __device__ __align__(16) float         g_z [(size_t)NN * DD];
static __device__ __align__(16) __nv_bfloat16 g_a0[(size_t)NPAD * DD];   // A hi plane
static __device__ __align__(16) __nv_bfloat16 g_a1[(size_t)NPAD * DD];   // A lo plane
static __device__ __align__(16) __nv_bfloat16 g_wt1_0[DD * DD];   // W1^T hi [N,K]
static __device__ __align__(16) __nv_bfloat16 g_wt1_1[DD * DD];
static __device__ __align__(16) __nv_bfloat16 g_wtc_0[DD * DD];   // [Wmu|Wlv]^T hi
static __device__ __align__(16) __nv_bfloat16 g_wtc_1[DD * DD];
static __device__ float g_bcat[DD];

// ---------------- helpers ---------------------------------------------------
__device__ __forceinline__ uint32_t smem_u32(const void* p) {
    uint32_t a;
    asm("{ .reg .u64 t; cvta.to.shared.u64 t, %1; cvt.u32.u64 %0, t; }"
        : "=r"(a) : "l"(p));
    return a;
}

__device__ __forceinline__ int load_idx(const void* ei, int pos) {
    if (g_is64) return (int)((const long long*)ei)[pos];
    return ((const int*)ei)[pos];
}

// ---------------- k1: zero deg + weight prep + parallel detect -------------
__global__ void prep_kernel(const void* __restrict__ ei,
                            const float* __restrict__ W1,
                            const float* __restrict__ Wmu,
                            const float* __restrict__ Wlv,
                            const float* __restrict__ bmu,
                            const float* __restrict__ blv) {
    int idx = blockIdx.x * 256 + threadIdx.x;      // 0..65535
    if (idx < NN) g_deg[idx] = 0;

    int n = idx >> 8, k = idx & 255;
    float v1 = W1[k * DD + n];
    __nv_bfloat16 h = __float2bfloat16(v1);
    g_wt1_0[idx] = h;
    g_wt1_1[idx] = __float2bfloat16(v1 - __bfloat162float(h));
    float v2 = (n < LAT) ? Wmu[k * LAT + n] : Wlv[k * LAT + (n - LAT)];
    h = __float2bfloat16(v2);
    g_wtc_0[idx] = h;
    g_wtc_1[idx] = __float2bfloat16(v2 - __bfloat162float(h));
    if (idx < DD) g_bcat[idx] = (idx < LAT) ? bmu[idx] : blv[idx - LAT];

    if (blockIdx.x == 0) {      // parallel int64-vs-int32 detection
        long long v = ((const long long*)ei)[threadIdx.x];
        int ok = (v >= 0 && v < NN) ? 1 : 0;
        int all = __syncthreads_and(ok);
        if (threadIdx.x == 0) g_is64 = all;
    }
}

// ---------------- k2: degree count -----------------------------------------
__global__ void count_deg_kernel(const void* __restrict__ ei) {
    int e = blockIdx.x * blockDim.x + threadIdx.x;
    if (e < NE) atomicAdd(&g_deg[load_idx(ei, NE + e)], 1);
}

// ---- k3-k5: wide 3-kernel exclusive scan of g_deg + dinv -------------------
__global__ void scan1_kernel() {
    __shared__ int s[256];
    int t = threadIdx.x;
    int i = blockIdx.x * 256 + t;
    s[t] = (i < NN) ? g_deg[i] : 0;
    __syncthreads();
    for (int o = 128; o > 0; o >>= 1) {
        if (t < o) s[t] += s[t + o];
        __syncthreads();
    }
    if (t == 0) g_bsum[blockIdx.x] = s[0];
}

__global__ void scan2_kernel() {
    __shared__ int s[256];
    int t = threadIdx.x;
    int v = (t < NBLK) ? g_bsum[t] : 0;
    s[t] = v;
    __syncthreads();
    for (int o = 1; o < 256; o <<= 1) {
        int x = (t >= o) ? s[t - o] : 0;
        __syncthreads();
        s[t] += x;
        __syncthreads();
    }
    g_boff[t] = s[t] - v;
}

__global__ void scan3_kernel() {
    __shared__ int s[256];
    int t = threadIdx.x;
    int i = blockIdx.x * 256 + t;
    int v = (i < NN) ? g_deg[i] : 0;
    s[t] = v;
    __syncthreads();
    for (int o = 1; o < 256; o <<= 1) {
        int x = (t >= o) ? s[t - o] : 0;
        __syncthreads();
        s[t] += x;
        __syncthreads();
    }
    int excl = s[t] - v + g_boff[blockIdx.x];
    if (i < NN) {
        g_rowstart[i] = excl;
        g_pos[i] = excl;
        g_dinv[i] = rsqrtf((float)v + 1.0f);
        if (i == NN - 1) g_rowstart[NN] = excl + v;
    }
}

// ---------------- k6: CSR fill ----------------------------------------------
__global__ void csr_fill_kernel(const void* __restrict__ ei) {
    int e = blockIdx.x * blockDim.x + threadIdx.x;
    if (e < NE) {
        int s = load_idx(ei, e);
        int d = load_idx(ei, NE + e);
        int slot = atomicAdd(&g_pos[d], 1);
        g_csrc[slot] = s;
        g_cnrm[slot] = g_dinv[s] * g_dinv[d];
    }
}

// ---------------- CSR aggregation -> split bf16 planes (R6 exact) ----------
__global__ void __launch_bounds__(256) agg_kernel(
        const float4* __restrict__ feat,
        __nv_bfloat16* __restrict__ p0, __nv_bfloat16* __restrict__ p1) {
    int gid = (blockIdx.x * blockDim.x + threadIdx.x) >> 6;
    int j   = threadIdx.x & 63;
    if (gid >= NN) return;

    int beg = g_rowstart[gid];
    int end = g_rowstart[gid + 1];
    float d  = g_dinv[gid];
    float d2 = d * d;

    float4 v = feat[(size_t)gid * 64 + j];
    float4 acc = make_float4(v.x * d2, v.y * d2, v.z * d2, v.w * d2);

    int e = beg;
    for (; e + 1 < end; e += 2) {
        int   s0 = g_csrc[e],     s1 = g_csrc[e + 1];
        float n0 = g_cnrm[e],     n1 = g_cnrm[e + 1];
        float4 u0 = feat[(size_t)s0 * 64 + j];
        float4 u1 = feat[(size_t)s1 * 64 + j];
        acc.x += n0 * u0.x + n1 * u1.x;
        acc.y += n0 * u0.y + n1 * u1.y;
        acc.z += n0 * u0.z + n1 * u1.z;
        acc.w += n0 * u0.w + n1 * u1.w;
    }
    if (e < end) {
        int   s0 = g_csrc[e];
        float n0 = g_cnrm[e];
        float4 u0 = feat[(size_t)s0 * 64 + j];
        acc.x += n0 * u0.x;
        acc.y += n0 * u0.y;
        acc.z += n0 * u0.z;
        acc.w += n0 * u0.w;
    }

    __nv_bfloat16 h[4], l[4];
    float vv[4] = {acc.x, acc.y, acc.z, acc.w};
    #pragma unroll
    for (int i = 0; i < 4; i++) {
        h[i] = __float2bfloat16(vv[i]);
        l[i] = __float2bfloat16(vv[i] - __bfloat162float(h[i]));
    }
    size_t off = (size_t)gid * DD + 4 * j;
    *(uint2*)(p0 + off) = *(uint2*)h;
    *(uint2*)(p1 + off) = *(uint2*)l;
}

// ---------------- mma.sync bf16 GEMM ---------------------------------------
// C[M,256] = (A0+A1) @ (B0+B1)^T  (B stored [N,K], K-contiguous)
// 3-product split: a0b0 + a0b1 + a1b0, fp32 accumulators.
// BM=128, BN=128, BK=32, 8 warps (warp tile 32x64), cp.async double buffer.
// B fragments loaded via ldmatrix.x4 over n-pairs (half the ldmatrix count).
#define SMEM_ARR   10240                 // 128 rows * 80 B
#define SMEM_STAGE (4 * SMEM_ARR)        // A0,A1,B0,B1
#define SMEM_TOT_G (2 * SMEM_STAGE)      // 81920 B

__device__ __forceinline__ void ldmx4(uint32_t* r, uint32_t addr) {
    asm volatile("ldmatrix.sync.aligned.m8n8.x4.shared.b16 {%0,%1,%2,%3}, [%4];"
                 : "=r"(r[0]), "=r"(r[1]), "=r"(r[2]), "=r"(r[3]) : "r"(addr));
}
__device__ __forceinline__ void mma16816(float* c, const uint32_t* a,
                                         const uint32_t* b) {
    asm volatile(
        "mma.sync.aligned.m16n8k16.row.col.f32.bf16.bf16.f32 "
        "{%0,%1,%2,%3}, {%4,%5,%6,%7}, {%8,%9}, {%0,%1,%2,%3};"
        : "+f"(c[0]), "+f"(c[1]), "+f"(c[2]), "+f"(c[3])
        : "r"(a[0]), "r"(a[1]), "r"(a[2]), "r"(a[3]), "r"(b[0]), "r"(b[1]));
}

template <int EPI>
__global__ void __launch_bounds__(256) gemm_mma_kernel(
        const __nv_bfloat16* __restrict__ A0, const __nv_bfloat16* __restrict__ A1,
        const __nv_bfloat16* __restrict__ B0, const __nv_bfloat16* __restrict__ B1,
        const float* __restrict__ bias,
        float* __restrict__ out0, float* __restrict__ out1) {
    extern __shared__ char smem[];
    uint32_t sb = smem_u32(smem);
    int tid = threadIdx.x;
    int lane = tid & 31, w = tid >> 5;
    int warp_m = w & 3, warp_n = w >> 2;
    int row0 = blockIdx.x * 128;
    int col0 = blockIdx.y * 128;

    auto load_chunk = [&](int st, int c) {
        #pragma unroll
        for (int it = 0; it < 8; it++) {
            int i   = tid + it * 256;
            int u   = i & 3;                 // 16B unit within 64B row-chunk
            int row = (i >> 2) & 127;
            int arr = i >> 9;                // 0:A0 1:A1 2:B0 3:B1
            const __nv_bfloat16* base = (arr == 0) ? A0 : (arr == 1) ? A1
                                      : (arr == 2) ? B0 : B1;
            int grow = (arr < 2) ? (row0 + row) : (col0 + row);
            const void* src = base + (size_t)grow * DD + c * 32 + u * 8;
            uint32_t dst = sb + st * SMEM_STAGE + arr * SMEM_ARR + row * 80 + u * 16;
            asm volatile("cp.async.cg.shared.global [%0], [%1], 16;"
                         :: "r"(dst), "l"(src));
        }
        asm volatile("cp.async.commit_group;" ::: "memory");
    };

    float acc[2][8][4];
    #pragma unroll
    for (int i = 0; i < 2; i++)
        #pragma unroll
        for (int j = 0; j < 8; j++)
            #pragma unroll
            for (int q = 0; q < 4; q++) acc[i][j][q] = 0.0f;

    load_chunk(0, 0);
    asm volatile("cp.async.wait_group 0;" ::: "memory");
    __syncthreads();

    int ar  = 32 * warp_m + (lane & 15);
    int ac  = (lane >> 4) << 3;
    // B ldmatrix.x4 lane mapping: lanes 0-7 -> (n0-7,k0), 8-15 -> (n0-7,k8),
    // 16-23 -> (n8-15,k0), 24-31 -> (n8-15,k8)
    int br4 = 64 * warp_n + (lane & 7) + (((lane >> 4) & 1) << 3);
    int bc  = ((lane >> 3) & 1) << 3;

    for (int c = 0; c < 8; c++) {
        int st = c & 1;
        if (c < 7) load_chunk(st ^ 1, c + 1);

        uint32_t sA0 = sb + st * SMEM_STAGE;
        uint32_t sA1 = sA0 + SMEM_ARR;
        uint32_t sB0 = sA0 + 2 * SMEM_ARR;
        uint32_t sB1 = sA0 + 3 * SMEM_ARR;

        #pragma unroll
        for (int s = 0; s < 2; s++) {
            uint32_t a0f[2][4], a1f[2][4];
            #pragma unroll
            for (int i = 0; i < 2; i++) {
                uint32_t off = (uint32_t)(ar + 16 * i) * 80 + (ac + 16 * s) * 2;
                ldmx4(a0f[i], sA0 + off);
                ldmx4(a1f[i], sA1 + off);
            }
            #pragma unroll
            for (int jp = 0; jp < 4; jp++) {      // n-pair: j = 2jp, 2jp+1
                uint32_t b0f[4], b1f[4];
                uint32_t off = (uint32_t)(br4 + 16 * jp) * 80 + (bc + 16 * s) * 2;
                ldmx4(b0f, sB0 + off);
                ldmx4(b1f, sB1 + off);
                #pragma unroll
                for (int h = 0; h < 2; h++) {     // half of pair
                    int j = 2 * jp + h;
                    #pragma unroll
                    for (int i = 0; i < 2; i++) {
                        mma16816(acc[i][j], a0f[i], b0f + 2 * h);
                        mma16816(acc[i][j], a0f[i], b1f + 2 * h);
                        mma16816(acc[i][j], a1f[i], b0f + 2 * h);
                    }
                }
            }
        }
        asm volatile("cp.async.wait_group 0;" ::: "memory");
        __syncthreads();
    }

    // ---- epilogue ----
    #pragma unroll
    for (int i = 0; i < 2; i++) {
        int r = row0 + 32 * warp_m + 16 * i + (lane >> 2);
        #pragma unroll
        for (int j = 0; j < 8; j++) {
            int cg = col0 + 64 * warp_n + 8 * j + ((lane & 3) << 1);
            float b0v = bias[cg], b1v = bias[cg + 1];
            float v0 = acc[i][j][0] + b0v, v1 = acc[i][j][1] + b1v;
            float v2 = acc[i][j][2] + b0v, v3 = acc[i][j][3] + b1v;
            if (EPI == 1) {
                v0 = fmaxf(v0, 0.0f); v1 = fmaxf(v1, 0.0f);
                v2 = fmaxf(v2, 0.0f); v3 = fmaxf(v3, 0.0f);
                if (r < NN)
                    *(float2*)(out0 + (size_t)r * DD + cg) = make_float2(v0, v1);
                if (r + 8 < NN)
                    *(float2*)(out0 + (size_t)(r + 8) * DD + cg) = make_float2(v2, v3);
            } else {
                float* o  = (cg < LAT) ? out0 + (size_t)r * LAT + cg
                                       : out1 + (size_t)r * LAT + (cg - LAT);
                float* o8 = (cg < LAT) ? out0 + (size_t)(r + 8) * LAT + cg
                                       : out1 + (size_t)(r + 8) * LAT + (cg - LAT);
                if (r < NN)     *(float2*)o  = make_float2(v0, v1);
                if (r + 8 < NN) *(float2*)o8 = make_float2(v2, v3);
            }
        }
    }
}

// ---------------- launch ---------------------------------------------------
extern "C" void kernel_launch(void* const* d_in, const int* in_sizes, int n_in,
                              void* d_out, int out_size) {
    const float* x    = (const float*)d_in[0];
    const void*  ei   = d_in[1];
    const float* W1   = (const float*)d_in[2];
    const float* b1   = (const float*)d_in[3];
    const float* Wmu  = (const float*)d_in[4];
    const float* bmu  = (const float*)d_in[5];
    const float* Wlv  = (const float*)d_in[6];
    const float* blv  = (const float*)d_in[7];
    float* out_mu = (float*)d_out;
    float* out_lv = (float*)d_out + (size_t)NN * LAT;

    float* z = nullptr;
    __nv_bfloat16 *a0 = nullptr, *a1 = nullptr;
    __nv_bfloat16 *wt10 = nullptr, *wt11 = nullptr, *wtc0 = nullptr, *wtc1 = nullptr;
    float* bcat = nullptr;
    cudaGetSymbolAddress((void**)&z,    g_z);
    cudaGetSymbolAddress((void**)&a0,   g_a0);
    cudaGetSymbolAddress((void**)&a1,   g_a1);
    cudaGetSymbolAddress((void**)&wt10, g_wt1_0);
    cudaGetSymbolAddress((void**)&wt11, g_wt1_1);
    cudaGetSymbolAddress((void**)&wtc0, g_wtc_0);
    cudaGetSymbolAddress((void**)&wtc1, g_wtc_1);
    cudaGetSymbolAddress((void**)&bcat, g_bcat);
    (void)n_in; (void)in_sizes; (void)out_size;

    cudaFuncSetAttribute(gemm_mma_kernel<1>,
                         cudaFuncAttributeMaxDynamicSharedMemorySize, SMEM_TOT_G);
    cudaFuncSetAttribute(gemm_mma_kernel<2>,
                         cudaFuncAttributeMaxDynamicSharedMemorySize, SMEM_TOT_G);

    // ---- graph prep (6 kernels) ----
    prep_kernel<<<256, 256>>>(ei, W1, Wmu, Wlv, bmu, blv);
    count_deg_kernel<<<(NE + 255) / 256, 256>>>(ei);
    scan1_kernel<<<NBLK, 256>>>();
    scan2_kernel<<<1, 256>>>();
    scan3_kernel<<<NBLK, 256>>>();
    csr_fill_kernel<<<(NE + 255) / 256, 256>>>(ei);

    // ---- layer 1 ----
    agg_kernel<<<(NN * 64 + 255) / 256, 256>>>((const float4*)x, a0, a1);
    gemm_mma_kernel<1><<<dim3(NPAD / 128, 2), 256, SMEM_TOT_G>>>(a0, a1, wt10, wt11,
                                                                 b1, z, nullptr);

    // ---- layers 2/3 (shared aggregation, fused N=256 GEMM) ----
    agg_kernel<<<(NN * 64 + 255) / 256, 256>>>((const float4*)z, a0, a1);
    gemm_mma_kernel<2><<<dim3(NPAD / 128, 2), 256, SMEM_TOT_G>>>(a0, a1, wtc0, wtc1,
                                                                 bcat, out_mu, out_lv);
}

// round 11
// speedup vs baseline: 2.3265x; 1.0774x over previous
#include <cuda_runtime.h>
#include <cuda_bf16.h>
#include <cuda_fp16.h>
#include <cstdint>

#define NN 50000
#define NPAD 50048          // 391 * 128
#define NE 800000
#define DD 256
#define LAT 128
#define NBLK 196            // ceil(NN/256)

// ---------------- scratch (static __device__ globals; no allocs) ----------
static __device__ int   g_is64;
static __device__ int   g_deg[NN];
static __device__ float g_dinv[NN];
static __device__ int   g_rowstart[NN + 1];
static __device__ int   g_pos[NN];
static __device__ int   g_bsum[256];
static __device__ int   g_boff[256];
static __device__ int   g_csrc[NE];
static __device__ float g_cnrm[NE];
static __device__ __align__(16) __half        g_xh[(size_t)NN * DD];     // x as fp16
static __device__ __align__(16) __half        g_zh[(size_t)NN * DD];     // z as fp16
static __device__ __align__(16) __nv_bfloat16 g_a0[(size_t)NPAD * DD];   // A hi plane
static __device__ __align__(16) __nv_bfloat16 g_a1[(size_t)NPAD * DD];   // A lo plane
static __device__ __align__(16) __nv_bfloat16 g_wt1_0[DD * DD];   // W1^T hi [N,K]
static __device__ __align__(16) __nv_bfloat16 g_wt1_1[DD * DD];
static __device__ __align__(16) __nv_bfloat16 g_wtc_0[DD * DD];   // [Wmu|Wlv]^T hi
static __device__ __align__(16) __nv_bfloat16 g_wtc_1[DD * DD];
static __device__ float g_bcat[DD];

// ---------------- helpers ---------------------------------------------------
__device__ __forceinline__ uint32_t smem_u32(const void* p) {
    uint32_t a;
    asm("{ .reg .u64 t; cvta.to.shared.u64 t, %1; cvt.u32.u64 %0, t; }"
        : "=r"(a) : "l"(p));
    return a;
}

__device__ __forceinline__ int load_idx(const void* ei, int pos) {
    if (g_is64) return (int)((const long long*)ei)[pos];
    return ((const int*)ei)[pos];
}

__device__ __forceinline__ float4 h8_to_f4(uint2 raw) {
    __half2 a = *(__half2*)&raw.x;
    __half2 b = *(__half2*)&raw.y;
    float2 fa = __half22float2(a);
    float2 fb = __half22float2(b);
    return make_float4(fa.x, fa.y, fb.x, fb.y);
}

// ---------------- k1: zero deg + weight prep + parallel detect -------------
__global__ void prep_kernel(const void* __restrict__ ei,
                            const float* __restrict__ W1,
                            const float* __restrict__ Wmu,
                            const float* __restrict__ Wlv,
                            const float* __restrict__ bmu,
                            const float* __restrict__ blv) {
    int idx = blockIdx.x * 256 + threadIdx.x;      // 0..65535
    if (idx < NN) g_deg[idx] = 0;

    int n = idx >> 8, k = idx & 255;
    float v1 = W1[k * DD + n];
    __nv_bfloat16 h = __float2bfloat16(v1);
    g_wt1_0[idx] = h;
    g_wt1_1[idx] = __float2bfloat16(v1 - __bfloat162float(h));
    float v2 = (n < LAT) ? Wmu[k * LAT + n] : Wlv[k * LAT + (n - LAT)];
    h = __float2bfloat16(v2);
    g_wtc_0[idx] = h;
    g_wtc_1[idx] = __float2bfloat16(v2 - __bfloat162float(h));
    if (idx < DD) g_bcat[idx] = (idx < LAT) ? bmu[idx] : blv[idx - LAT];

    if (blockIdx.x == 0) {      // parallel int64-vs-int32 detection
        long long v = ((const long long*)ei)[threadIdx.x];
        int ok = (v >= 0 && v < NN) ? 1 : 0;
        int all = __syncthreads_and(ok);
        if (threadIdx.x == 0) g_is64 = all;
    }
}

// ---------------- k2: convert x -> fp16 ------------------------------------
__global__ void xconv_kernel(const float4* __restrict__ x4) {
    int idx = blockIdx.x * blockDim.x + threadIdx.x;   // one float4 each
    if (idx < NN * (DD / 4)) {
        float4 v = x4[idx];
        uint2 out;
        *(__half2*)&out.x = __floats2half2_rn(v.x, v.y);
        *(__half2*)&out.y = __floats2half2_rn(v.z, v.w);
        ((uint2*)g_xh)[idx] = out;
    }
}

// ---------------- k3: degree count -----------------------------------------
__global__ void count_deg_kernel(const void* __restrict__ ei) {
    int e = blockIdx.x * blockDim.x + threadIdx.x;
    if (e < NE) atomicAdd(&g_deg[load_idx(ei, NE + e)], 1);
}

// ---- k4-k6: wide 3-kernel exclusive scan of g_deg + dinv -------------------
__global__ void scan1_kernel() {
    __shared__ int s[256];
    int t = threadIdx.x;
    int i = blockIdx.x * 256 + t;
    s[t] = (i < NN) ? g_deg[i] : 0;
    __syncthreads();
    for (int o = 128; o > 0; o >>= 1) {
        if (t < o) s[t] += s[t + o];
        __syncthreads();
    }
    if (t == 0) g_bsum[blockIdx.x] = s[0];
}

__global__ void scan2_kernel() {
    __shared__ int s[256];
    int t = threadIdx.x;
    int v = (t < NBLK) ? g_bsum[t] : 0;
    s[t] = v;
    __syncthreads();
    for (int o = 1; o < 256; o <<= 1) {
        int x = (t >= o) ? s[t - o] : 0;
        __syncthreads();
        s[t] += x;
        __syncthreads();
    }
    g_boff[t] = s[t] - v;
}

__global__ void scan3_kernel() {
    __shared__ int s[256];
    int t = threadIdx.x;
    int i = blockIdx.x * 256 + t;
    int v = (i < NN) ? g_deg[i] : 0;
    s[t] = v;
    __syncthreads();
    for (int o = 1; o < 256; o <<= 1) {
        int x = (t >= o) ? s[t - o] : 0;
        __syncthreads();
        s[t] += x;
        __syncthreads();
    }
    int excl = s[t] - v + g_boff[blockIdx.x];
    if (i < NN) {
        g_rowstart[i] = excl;
        g_pos[i] = excl;
        g_dinv[i] = rsqrtf((float)v + 1.0f);
        if (i == NN - 1) g_rowstart[NN] = excl + v;
    }
}

// ---------------- k7: CSR fill ----------------------------------------------
__global__ void csr_fill_kernel(const void* __restrict__ ei) {
    int e = blockIdx.x * blockDim.x + threadIdx.x;
    if (e < NE) {
        int s = load_idx(ei, e);
        int d = load_idx(ei, NE + e);
        int slot = atomicAdd(&g_pos[d], 1);
        g_csrc[slot] = s;
        g_cnrm[slot] = g_dinv[s] * g_dinv[d];
    }
}

// ---------------- CSR aggregation (fp16 gather) -> split bf16 planes --------
// feat: fp16 rows of DD values (= 64 uint2 of 4 halves). j in 0..63.
__global__ void __launch_bounds__(256) agg_kernel(
        const uint2* __restrict__ feat,
        __nv_bfloat16* __restrict__ p0, __nv_bfloat16* __restrict__ p1) {
    int gid = (blockIdx.x * blockDim.x + threadIdx.x) >> 6;
    int j   = threadIdx.x & 63;
    if (gid >= NN) return;

    int beg = g_rowstart[gid];
    int end = g_rowstart[gid + 1];
    float d  = g_dinv[gid];
    float d2 = d * d;

    float4 v = h8_to_f4(feat[(size_t)gid * 64 + j]);
    float4 acc = make_float4(v.x * d2, v.y * d2, v.z * d2, v.w * d2);

    int e = beg;
    for (; e + 1 < end; e += 2) {
        int   s0 = g_csrc[e],     s1 = g_csrc[e + 1];
        float n0 = g_cnrm[e],     n1 = g_cnrm[e + 1];
        float4 u0 = h8_to_f4(feat[(size_t)s0 * 64 + j]);
        float4 u1 = h8_to_f4(feat[(size_t)s1 * 64 + j]);
        acc.x += n0 * u0.x + n1 * u1.x;
        acc.y += n0 * u0.y + n1 * u1.y;
        acc.z += n0 * u0.z + n1 * u1.z;
        acc.w += n0 * u0.w + n1 * u1.w;
    }
    if (e < end) {
        int   s0 = g_csrc[e];
        float n0 = g_cnrm[e];
        float4 u0 = h8_to_f4(feat[(size_t)s0 * 64 + j]);
        acc.x += n0 * u0.x;
        acc.y += n0 * u0.y;
        acc.z += n0 * u0.z;
        acc.w += n0 * u0.w;
    }

    __nv_bfloat16 h[4], l[4];
    float vv[4] = {acc.x, acc.y, acc.z, acc.w};
    #pragma unroll
    for (int i = 0; i < 4; i++) {
        h[i] = __float2bfloat16(vv[i]);
        l[i] = __float2bfloat16(vv[i] - __bfloat162float(h[i]));
    }
    size_t off = (size_t)gid * DD + 4 * j;
    *(uint2*)(p0 + off) = *(uint2*)h;
    *(uint2*)(p1 + off) = *(uint2*)l;
}

// ---------------- mma.sync bf16 GEMM ---------------------------------------
// C[M,256] = (A0+A1) @ (B0+B1)^T  (B stored [N,K], K-contiguous)
// 3-product split: a0b0 + a0b1 + a1b0, fp32 accumulators.
// BM=128, BN=128, BK=32, 8 warps (warp tile 32x64), cp.async double buffer.
// EPI 1: z (fp16) = relu(C + bias). EPI 2: fp32 cols 0..127 -> mu, 128..255 -> lv.
#define SMEM_ARR   10240                 // 128 rows * 80 B
#define SMEM_STAGE (4 * SMEM_ARR)        // A0,A1,B0,B1
#define SMEM_TOT_G (2 * SMEM_STAGE)      // 81920 B

__device__ __forceinline__ void ldmx4(uint32_t* r, uint32_t addr) {
    asm volatile("ldmatrix.sync.aligned.m8n8.x4.shared.b16 {%0,%1,%2,%3}, [%4];"
                 : "=r"(r[0]), "=r"(r[1]), "=r"(r[2]), "=r"(r[3]) : "r"(addr));
}
__device__ __forceinline__ void mma16816(float* c, const uint32_t* a,
                                         const uint32_t* b) {
    asm volatile(
        "mma.sync.aligned.m16n8k16.row.col.f32.bf16.bf16.f32 "
        "{%0,%1,%2,%3}, {%4,%5,%6,%7}, {%8,%9}, {%0,%1,%2,%3};"
        : "+f"(c[0]), "+f"(c[1]), "+f"(c[2]), "+f"(c[3])
        : "r"(a[0]), "r"(a[1]), "r"(a[2]), "r"(a[3]), "r"(b[0]), "r"(b[1]));
}

template <int EPI>
__global__ void __launch_bounds__(256) gemm_mma_kernel(
        const __nv_bfloat16* __restrict__ A0, const __nv_bfloat16* __restrict__ A1,
        const __nv_bfloat16* __restrict__ B0, const __nv_bfloat16* __restrict__ B1,
        const float* __restrict__ bias,
        float* __restrict__ out0, float* __restrict__ out1,
        __half* __restrict__ outh) {
    extern __shared__ char smem[];
    uint32_t sb = smem_u32(smem);
    int tid = threadIdx.x;
    int lane = tid & 31, w = tid >> 5;
    int warp_m = w & 3, warp_n = w >> 2;
    int row0 = blockIdx.x * 128;
    int col0 = blockIdx.y * 128;

    auto load_chunk = [&](int st, int c) {
        #pragma unroll
        for (int it = 0; it < 8; it++) {
            int i   = tid + it * 256;
            int u   = i & 3;                 // 16B unit within 64B row-chunk
            int row = (i >> 2) & 127;
            int arr = i >> 9;                // 0:A0 1:A1 2:B0 3:B1
            const __nv_bfloat16* base = (arr == 0) ? A0 : (arr == 1) ? A1
                                      : (arr == 2) ? B0 : B1;
            int grow = (arr < 2) ? (row0 + row) : (col0 + row);
            const void* src = base + (size_t)grow * DD + c * 32 + u * 8;
            uint32_t dst = sb + st * SMEM_STAGE + arr * SMEM_ARR + row * 80 + u * 16;
            asm volatile("cp.async.cg.shared.global [%0], [%1], 16;"
                         :: "r"(dst), "l"(src));
        }
        asm volatile("cp.async.commit_group;" ::: "memory");
    };

    float acc[2][8][4];
    #pragma unroll
    for (int i = 0; i < 2; i++)
        #pragma unroll
        for (int j = 0; j < 8; j++)
            #pragma unroll
            for (int q = 0; q < 4; q++) acc[i][j][q] = 0.0f;

    load_chunk(0, 0);
    asm volatile("cp.async.wait_group 0;" ::: "memory");
    __syncthreads();

    int ar  = 32 * warp_m + (lane & 15);
    int ac  = (lane >> 4) << 3;
    // B ldmatrix.x4 lane mapping: lanes 0-7 -> (n0-7,k0), 8-15 -> (n0-7,k8),
    // 16-23 -> (n8-15,k0), 24-31 -> (n8-15,k8)
    int br4 = 64 * warp_n + (lane & 7) + (((lane >> 4) & 1) << 3);
    int bc  = ((lane >> 3) & 1) << 3;

    for (int c = 0; c < 8; c++) {
        int st = c & 1;
        if (c < 7) load_chunk(st ^ 1, c + 1);

        uint32_t sA0 = sb + st * SMEM_STAGE;
        uint32_t sA1 = sA0 + SMEM_ARR;
        uint32_t sB0 = sA0 + 2 * SMEM_ARR;
        uint32_t sB1 = sA0 + 3 * SMEM_ARR;

        #pragma unroll
        for (int s = 0; s < 2; s++) {
            uint32_t a0f[2][4], a1f[2][4];
            #pragma unroll
            for (int i = 0; i < 2; i++) {
                uint32_t off = (uint32_t)(ar + 16 * i) * 80 + (ac + 16 * s) * 2;
                ldmx4(a0f[i], sA0 + off);
                ldmx4(a1f[i], sA1 + off);
            }
            #pragma unroll
            for (int jp = 0; jp < 4; jp++) {      // n-pair: j = 2jp, 2jp+1
                uint32_t b0f[4], b1f[4];
                uint32_t off = (uint32_t)(br4 + 16 * jp) * 80 + (bc + 16 * s) * 2;
                ldmx4(b0f, sB0 + off);
                ldmx4(b1f, sB1 + off);
                #pragma unroll
                for (int h = 0; h < 2; h++) {     // half of pair
                    int j = 2 * jp + h;
                    #pragma unroll
                    for (int i = 0; i < 2; i++) {
                        mma16816(acc[i][j], a0f[i], b0f + 2 * h);
                        mma16816(acc[i][j], a0f[i], b1f + 2 * h);
                        mma16816(acc[i][j], a1f[i], b0f + 2 * h);
                    }
                }
            }
        }
        asm volatile("cp.async.wait_group 0;" ::: "memory");
        __syncthreads();
    }

    // ---- epilogue ----
    #pragma unroll
    for (int i = 0; i < 2; i++) {
        int r = row0 + 32 * warp_m + 16 * i + (lane >> 2);
        #pragma unroll
        for (int j = 0; j < 8; j++) {
            int cg = col0 + 64 * warp_n + 8 * j + ((lane & 3) << 1);
            float b0v = bias[cg], b1v = bias[cg + 1];
            float v0 = acc[i][j][0] + b0v, v1 = acc[i][j][1] + b1v;
            float v2 = acc[i][j][2] + b0v, v3 = acc[i][j][3] + b1v;
            if (EPI == 1) {
                v0 = fmaxf(v0, 0.0f); v1 = fmaxf(v1, 0.0f);
                v2 = fmaxf(v2, 0.0f); v3 = fmaxf(v3, 0.0f);
                if (r < NN)
                    *(__half2*)(outh + (size_t)r * DD + cg) = __floats2half2_rn(v0, v1);
                if (r + 8 < NN)
                    *(__half2*)(outh + (size_t)(r + 8) * DD + cg) = __floats2half2_rn(v2, v3);
            } else {
                float* o  = (cg < LAT) ? out0 + (size_t)r * LAT + cg
                                       : out1 + (size_t)r * LAT + (cg - LAT);
                float* o8 = (cg < LAT) ? out0 + (size_t)(r + 8) * LAT + cg
                                       : out1 + (size_t)(r + 8) * LAT + (cg - LAT);
                if (r < NN)     *(float2*)o  = make_float2(v0, v1);
                if (r + 8 < NN) *(float2*)o8 = make_float2(v2, v3);
            }
        }
    }
}

// ---------------- launch ---------------------------------------------------
extern "C" void kernel_launch(void* const* d_in, const int* in_sizes, int n_in,
                              void* d_out, int out_size) {
    const float* x    = (const float*)d_in[0];
    const void*  ei   = d_in[1];
    const float* W1   = (const float*)d_in[2];
    const float* b1   = (const float*)d_in[3];
    const float* Wmu  = (const float*)d_in[4];
    const float* bmu  = (const float*)d_in[5];
    const float* Wlv  = (const float*)d_in[6];
    const float* blv  = (const float*)d_in[7];
    float* out_mu = (float*)d_out;
    float* out_lv = (float*)d_out + (size_t)NN * LAT;

    __half *xh = nullptr, *zh = nullptr;
    __nv_bfloat16 *a0 = nullptr, *a1 = nullptr;
    __nv_bfloat16 *wt10 = nullptr, *wt11 = nullptr, *wtc0 = nullptr, *wtc1 = nullptr;
    float* bcat = nullptr;
    cudaGetSymbolAddress((void**)&xh,   g_xh);
    cudaGetSymbolAddress((void**)&zh,   g_zh);
    cudaGetSymbolAddress((void**)&a0,   g_a0);
    cudaGetSymbolAddress((void**)&a1,   g_a1);
    cudaGetSymbolAddress((void**)&wt10, g_wt1_0);
    cudaGetSymbolAddress((void**)&wt11, g_wt1_1);
    cudaGetSymbolAddress((void**)&wtc0, g_wtc_0);
    cudaGetSymbolAddress((void**)&wtc1, g_wtc_1);
    cudaGetSymbolAddress((void**)&bcat, g_bcat);
    (void)n_in; (void)in_sizes; (void)out_size;

    cudaFuncSetAttribute(gemm_mma_kernel<1>,
                         cudaFuncAttributeMaxDynamicSharedMemorySize, SMEM_TOT_G);
    cudaFuncSetAttribute(gemm_mma_kernel<2>,
                         cudaFuncAttributeMaxDynamicSharedMemorySize, SMEM_TOT_G);

    // ---- graph prep ----
    prep_kernel<<<256, 256>>>(ei, W1, Wmu, Wlv, bmu, blv);
    xconv_kernel<<<(NN * 64 + 255) / 256, 256>>>((const float4*)x);
    count_deg_kernel<<<(NE + 255) / 256, 256>>>(ei);
    scan1_kernel<<<NBLK, 256>>>();
    scan2_kernel<<<1, 256>>>();
    scan3_kernel<<<NBLK, 256>>>();
    csr_fill_kernel<<<(NE + 255) / 256, 256>>>(ei);

    // ---- layer 1: agg(x fp16) -> planes ; GEMM -> z (fp16) ----
    agg_kernel<<<(NN * 64 + 255) / 256, 256>>>((const uint2*)xh, a0, a1);
    gemm_mma_kernel<1><<<dim3(NPAD / 128, 2), 256, SMEM_TOT_G>>>(a0, a1, wt10, wt11,
                                                                 b1, nullptr, nullptr, zh);

    // ---- layers 2/3: agg(z fp16) -> planes ; fused N=256 GEMM -> mu, lv ----
    agg_kernel<<<(NN * 64 + 255) / 256, 256>>>((const uint2*)zh, a0, a1);
    gemm_mma_kernel<2><<<dim3(NPAD / 128, 2), 256, SMEM_TOT_G>>>(a0, a1, wtc0, wtc1,
                                                                 bcat, out_mu, out_lv, nullptr);
}

// round 13
// speedup vs baseline: 3.0049x; 1.2916x over previous
#include <cuda_runtime.h>
#include <cuda_fp16.h>
#include <cstdint>

#define NN 50000
#define NPAD 50048          // 391 * 128
#define NE 800000
#define DD 256
#define LAT 128
#define NBLK 196            // ceil(NN/256)

// ---------------- scratch (static __device__ globals; no allocs) ----------
static __device__ int   g_is64;
static __device__ int   g_deg[NN];
static __device__ float g_dinv[NN];
static __device__ int   g_rowstart[NN + 1];
static __device__ int   g_pos[NN];
static __device__ int   g_bsum[256];
static __device__ int   g_boff[256];
static __device__ int   g_csrc[NE];
static __device__ float g_cnrm[NE];
static __device__ __align__(16) __half g_xh[(size_t)NN * DD];     // x as fp16
static __device__ __align__(16) __half g_zh[(size_t)NN * DD];     // z as fp16
static __device__ __align__(16) __half g_ah[(size_t)NPAD * DD];   // aggregated A (fp16)
static __device__ __align__(16) __half g_wt1h[DD * DD];           // W1^T [N,K] fp16
static __device__ __align__(16) __half g_wtch[DD * DD];           // [Wmu|Wlv]^T fp16
static __device__ float g_bcat[DD];

// ---------------- helpers ---------------------------------------------------
__device__ __forceinline__ uint32_t smem_u32(const void* p) {
    uint32_t a;
    asm("{ .reg .u64 t; cvta.to.shared.u64 t, %1; cvt.u32.u64 %0, t; }"
        : "=r"(a) : "l"(p));
    return a;
}

__device__ __forceinline__ int load_idx(const void* ei, int pos) {
    if (g_is64) return (int)((const long long*)ei)[pos];
    return ((const int*)ei)[pos];
}

__device__ __forceinline__ float4 h8_to_f4(uint2 raw) {
    __half2 a = *(__half2*)&raw.x;
    __half2 b = *(__half2*)&raw.y;
    float2 fa = __half22float2(a);
    float2 fb = __half22float2(b);
    return make_float4(fa.x, fa.y, fb.x, fb.y);
}

// ---------------- k1: zero deg + weight prep (fp16) + parallel detect ------
__global__ void prep_kernel(const void* __restrict__ ei,
                            const float* __restrict__ W1,
                            const float* __restrict__ Wmu,
                            const float* __restrict__ Wlv,
                            const float* __restrict__ bmu,
                            const float* __restrict__ blv) {
    int idx = blockIdx.x * 256 + threadIdx.x;      // 0..65535
    if (idx < NN) g_deg[idx] = 0;

    int n = idx >> 8, k = idx & 255;
    g_wt1h[idx] = __float2half(W1[k * DD + n]);
    float v2 = (n < LAT) ? Wmu[k * LAT + n] : Wlv[k * LAT + (n - LAT)];
    g_wtch[idx] = __float2half(v2);
    if (idx < DD) g_bcat[idx] = (idx < LAT) ? bmu[idx] : blv[idx - LAT];

    if (blockIdx.x == 0) {      // parallel int64-vs-int32 detection
        long long v = ((const long long*)ei)[threadIdx.x];
        int ok = (v >= 0 && v < NN) ? 1 : 0;
        int all = __syncthreads_and(ok);
        if (threadIdx.x == 0) g_is64 = all;
    }
}

// ---------------- k2: convert x -> fp16 ------------------------------------
__global__ void xconv_kernel(const float4* __restrict__ x4) {
    int idx = blockIdx.x * blockDim.x + threadIdx.x;   // one float4 each
    if (idx < NN * (DD / 4)) {
        float4 v = x4[idx];
        uint2 out;
        *(__half2*)&out.x = __floats2half2_rn(v.x, v.y);
        *(__half2*)&out.y = __floats2half2_rn(v.z, v.w);
        ((uint2*)g_xh)[idx] = out;
    }
}

// ---------------- k3: degree count -----------------------------------------
__global__ void count_deg_kernel(const void* __restrict__ ei) {
    int e = blockIdx.x * blockDim.x + threadIdx.x;
    if (e < NE) atomicAdd(&g_deg[load_idx(ei, NE + e)], 1);
}

// ---- k4-k6: wide 3-kernel exclusive scan of g_deg + dinv -------------------
__global__ void scan1_kernel() {
    __shared__ int s[256];
    int t = threadIdx.x;
    int i = blockIdx.x * 256 + t;
    s[t] = (i < NN) ? g_deg[i] : 0;
    __syncthreads();
    for (int o = 128; o > 0; o >>= 1) {
        if (t < o) s[t] += s[t + o];
        __syncthreads();
    }
    if (t == 0) g_bsum[blockIdx.x] = s[0];
}

__global__ void scan2_kernel() {
    __shared__ int s[256];
    int t = threadIdx.x;
    int v = (t < NBLK) ? g_bsum[t] : 0;
    s[t] = v;
    __syncthreads();
    for (int o = 1; o < 256; o <<= 1) {
        int x = (t >= o) ? s[t - o] : 0;
        __syncthreads();
        s[t] += x;
        __syncthreads();
    }
    g_boff[t] = s[t] - v;
}

__global__ void scan3_kernel() {
    __shared__ int s[256];
    int t = threadIdx.x;
    int i = blockIdx.x * 256 + t;
    int v = (i < NN) ? g_deg[i] : 0;
    s[t] = v;
    __syncthreads();
    for (int o = 1; o < 256; o <<= 1) {
        int x = (t >= o) ? s[t - o] : 0;
        __syncthreads();
        s[t] += x;
        __syncthreads();
    }
    int excl = s[t] - v + g_boff[blockIdx.x];
    if (i < NN) {
        g_rowstart[i] = excl;
        g_pos[i] = excl;
        g_dinv[i] = rsqrtf((float)v + 1.0f);
        if (i == NN - 1) g_rowstart[NN] = excl + v;
    }
}

// ---------------- k7: CSR fill ----------------------------------------------
__global__ void csr_fill_kernel(const void* __restrict__ ei) {
    int e = blockIdx.x * blockDim.x + threadIdx.x;
    if (e < NE) {
        int s = load_idx(ei, e);
        int d = load_idx(ei, NE + e);
        int slot = atomicAdd(&g_pos[d], 1);
        g_csrc[slot] = s;
        g_cnrm[slot] = g_dinv[s] * g_dinv[d];
    }
}

// ---------------- CSR aggregation (fp16 gather) -> fp16 A -------------------
__global__ void __launch_bounds__(256) agg_kernel(
        const uint2* __restrict__ feat, __half* __restrict__ out) {
    int gid = (blockIdx.x * blockDim.x + threadIdx.x) >> 6;
    int j   = threadIdx.x & 63;
    if (gid >= NN) return;

    int beg = g_rowstart[gid];
    int end = g_rowstart[gid + 1];
    float d  = g_dinv[gid];
    float d2 = d * d;

    float4 v = h8_to_f4(feat[(size_t)gid * 64 + j]);
    float4 acc = make_float4(v.x * d2, v.y * d2, v.z * d2, v.w * d2);

    int e = beg;
    for (; e + 1 < end; e += 2) {
        int   s0 = g_csrc[e],     s1 = g_csrc[e + 1];
        float n0 = g_cnrm[e],     n1 = g_cnrm[e + 1];
        float4 u0 = h8_to_f4(feat[(size_t)s0 * 64 + j]);
        float4 u1 = h8_to_f4(feat[(size_t)s1 * 64 + j]);
        acc.x += n0 * u0.x + n1 * u1.x;
        acc.y += n0 * u0.y + n1 * u1.y;
        acc.z += n0 * u0.z + n1 * u1.z;
        acc.w += n0 * u0.w + n1 * u1.w;
    }
    if (e < end) {
        int   s0 = g_csrc[e];
        float n0 = g_cnrm[e];
        float4 u0 = h8_to_f4(feat[(size_t)s0 * 64 + j]);
        acc.x += n0 * u0.x;
        acc.y += n0 * u0.y;
        acc.z += n0 * u0.z;
        acc.w += n0 * u0.w;
    }

    uint2 o;
    *(__half2*)&o.x = __floats2half2_rn(acc.x, acc.y);
    *(__half2*)&o.y = __floats2half2_rn(acc.z, acc.w);
    *(uint2*)(out + (size_t)gid * DD + 4 * j) = o;
}

// ---------------- mma.sync fp16 GEMM ---------------------------------------
// C[M,256] = A[M,256] @ B^T  (B stored [N,K], K-contiguous), fp16 in, fp32 acc.
// BM=128, BN=128, BK=32, 8 warps (warp tile 32x64), cp.async double buffer.
// EPI 1: z (fp16) = relu(C + bias). EPI 2: fp32 cols 0..127 -> mu, 128..255 -> lv.
#define SMEM_ARR   10240                 // 128 rows * 80 B
#define SMEM_STAGE (2 * SMEM_ARR)        // A, B
#define SMEM_TOT_G (2 * SMEM_STAGE)      // 40960 B

__device__ __forceinline__ void ldmx4(uint32_t* r, uint32_t addr) {
    asm volatile("ldmatrix.sync.aligned.m8n8.x4.shared.b16 {%0,%1,%2,%3}, [%4];"
                 : "=r"(r[0]), "=r"(r[1]), "=r"(r[2]), "=r"(r[3]) : "r"(addr));
}
__device__ __forceinline__ void mma16816h(float* c, const uint32_t* a,
                                          const uint32_t* b) {
    asm volatile(
        "mma.sync.aligned.m16n8k16.row.col.f32.f16.f16.f32 "
        "{%0,%1,%2,%3}, {%4,%5,%6,%7}, {%8,%9}, {%0,%1,%2,%3};"
        : "+f"(c[0]), "+f"(c[1]), "+f"(c[2]), "+f"(c[3])
        : "r"(a[0]), "r"(a[1]), "r"(a[2]), "r"(a[3]), "r"(b[0]), "r"(b[1]));
}

template <int EPI>
__global__ void __launch_bounds__(256) gemm_mma_kernel(
        const __half* __restrict__ A, const __half* __restrict__ B,
        const float* __restrict__ bias,
        float* __restrict__ out0, float* __restrict__ out1,
        __half* __restrict__ outh) {
    extern __shared__ char smem[];
    uint32_t sb = smem_u32(smem);
    int tid = threadIdx.x;
    int lane = tid & 31, w = tid >> 5;
    int warp_m = w & 3, warp_n = w >> 2;
    int row0 = blockIdx.x * 128;
    int col0 = blockIdx.y * 128;

    auto load_chunk = [&](int st, int c) {
        #pragma unroll
        for (int it = 0; it < 4; it++) {
            int i   = tid + it * 256;        // 0..1023
            int u   = i & 3;                 // 16B unit within 64B row-chunk
            int row = (i >> 2) & 127;
            int arr = i >> 9;                // 0:A 1:B
            const __half* base = arr ? B : A;
            int grow = arr ? (col0 + row) : (row0 + row);
            const void* src = base + (size_t)grow * DD + c * 32 + u * 8;
            uint32_t dst = sb + st * SMEM_STAGE + arr * SMEM_ARR + row * 80 + u * 16;
            asm volatile("cp.async.cg.shared.global [%0], [%1], 16;"
                         :: "r"(dst), "l"(src));
        }
        asm volatile("cp.async.commit_group;" ::: "memory");
    };

    float acc[2][8][4];
    #pragma unroll
    for (int i = 0; i < 2; i++)
        #pragma unroll
        for (int j = 0; j < 8; j++)
            #pragma unroll
            for (int q = 0; q < 4; q++) acc[i][j][q] = 0.0f;

    load_chunk(0, 0);
    asm volatile("cp.async.wait_group 0;" ::: "memory");
    __syncthreads();

    int ar  = 32 * warp_m + (lane & 15);
    int ac  = (lane >> 4) << 3;
    // B ldmatrix.x4 lane mapping: lanes 0-7 -> (n0-7,k0), 8-15 -> (n0-7,k8),
    // 16-23 -> (n8-15,k0), 24-31 -> (n8-15,k8)
    int br4 = 64 * warp_n + (lane & 7) + (((lane >> 4) & 1) << 3);
    int bc  = ((lane >> 3) & 1) << 3;

    for (int c = 0; c < 8; c++) {
        int st = c & 1;
        if (c < 7) load_chunk(st ^ 1, c + 1);

        uint32_t sA = sb + st * SMEM_STAGE;
        uint32_t sB = sA + SMEM_ARR;

        #pragma unroll
        for (int s = 0; s < 2; s++) {
            uint32_t af[2][4];
            #pragma unroll
            for (int i = 0; i < 2; i++) {
                uint32_t off = (uint32_t)(ar + 16 * i) * 80 + (ac + 16 * s) * 2;
                ldmx4(af[i], sA + off);
            }
            #pragma unroll
            for (int jp = 0; jp < 4; jp++) {      // n-pair: j = 2jp, 2jp+1
                uint32_t bf[4];
                uint32_t off = (uint32_t)(br4 + 16 * jp) * 80 + (bc + 16 * s) * 2;
                ldmx4(bf, sB + off);
                #pragma unroll
                for (int h = 0; h < 2; h++) {     // half of pair
                    int j = 2 * jp + h;
                    #pragma unroll
                    for (int i = 0; i < 2; i++)
                        mma16816h(acc[i][j], af[i], bf + 2 * h);
                }
            }
        }
        asm volatile("cp.async.wait_group 0;" ::: "memory");
        __syncthreads();
    }

    // ---- epilogue ----
    #pragma unroll
    for (int i = 0; i < 2; i++) {
        int r = row0 + 32 * warp_m + 16 * i + (lane >> 2);
        #pragma unroll
        for (int j = 0; j < 8; j++) {
            int cg = col0 + 64 * warp_n + 8 * j + ((lane & 3) << 1);
            float b0v = bias[cg], b1v = bias[cg + 1];
            float v0 = acc[i][j][0] + b0v, v1 = acc[i][j][1] + b1v;
            float v2 = acc[i][j][2] + b0v, v3 = acc[i][j][3] + b1v;
            if (EPI == 1) {
                v0 = fmaxf(v0, 0.0f); v1 = fmaxf(v1, 0.0f);
                v2 = fmaxf(v2, 0.0f); v3 = fmaxf(v3, 0.0f);
                if (r < NN)
                    *(__half2*)(outh + (size_t)r * DD + cg) = __floats2half2_rn(v0, v1);
                if (r + 8 < NN)
                    *(__half2*)(outh + (size_t)(r + 8) * DD + cg) = __floats2half2_rn(v2, v3);
            } else {
                float* o  = (cg < LAT) ? out0 + (size_t)r * LAT + cg
                                       : out1 + (size_t)r * LAT + (cg - LAT);
                float* o8 = (cg < LAT) ? out0 + (size_t)(r + 8) * LAT + cg
                                       : out1 + (size_t)(r + 8) * LAT + (cg - LAT);
                if (r < NN)     *(float2*)o  = make_float2(v0, v1);
                if (r + 8 < NN) *(float2*)o8 = make_float2(v2, v3);
            }
        }
    }
}

// ---------------- launch ---------------------------------------------------
extern "C" void kernel_launch(void* const* d_in, const int* in_sizes, int n_in,
                              void* d_out, int out_size) {
    const float* x    = (const float*)d_in[0];
    const void*  ei   = d_in[1];
    const float* W1   = (const float*)d_in[2];
    const float* b1   = (const float*)d_in[3];
    const float* Wmu  = (const float*)d_in[4];
    const float* bmu  = (const float*)d_in[5];
    const float* Wlv  = (const float*)d_in[6];
    const float* blv  = (const float*)d_in[7];
    float* out_mu = (float*)d_out;
    float* out_lv = (float*)d_out + (size_t)NN * LAT;

    __half *xh = nullptr, *zh = nullptr, *ah = nullptr;
    __half *wt1h = nullptr, *wtch = nullptr;
    float* bcat = nullptr;
    cudaGetSymbolAddress((void**)&xh,   g_xh);
    cudaGetSymbolAddress((void**)&zh,   g_zh);
    cudaGetSymbolAddress((void**)&ah,   g_ah);
    cudaGetSymbolAddress((void**)&wt1h, g_wt1h);
    cudaGetSymbolAddress((void**)&wtch, g_wtch);
    cudaGetSymbolAddress((void**)&bcat, g_bcat);
    (void)n_in; (void)in_sizes; (void)out_size;

    cudaFuncSetAttribute(gemm_mma_kernel<1>,
                         cudaFuncAttributeMaxDynamicSharedMemorySize, SMEM_TOT_G);
    cudaFuncSetAttribute(gemm_mma_kernel<2>,
                         cudaFuncAttributeMaxDynamicSharedMemorySize, SMEM_TOT_G);

    // ---- graph prep ----
    prep_kernel<<<256, 256>>>(ei, W1, Wmu, Wlv, bmu, blv);
    xconv_kernel<<<(NN * 64 + 255) / 256, 256>>>((const float4*)x);
    count_deg_kernel<<<(NE + 255) / 256, 256>>>(ei);
    scan1_kernel<<<NBLK, 256>>>();
    scan2_kernel<<<1, 256>>>();
    scan3_kernel<<<NBLK, 256>>>();
    csr_fill_kernel<<<(NE + 255) / 256, 256>>>(ei);

    // ---- layer 1: agg(x fp16) -> A ; GEMM -> z (fp16) ----
    agg_kernel<<<(NN * 64 + 255) / 256, 256>>>((const uint2*)xh, ah);
    gemm_mma_kernel<1><<<dim3(NPAD / 128, 2), 256, SMEM_TOT_G>>>(ah, wt1h,
                                                                 b1, nullptr, nullptr, zh);

    // ---- layers 2/3: agg(z fp16) -> A ; fused N=256 GEMM -> mu, lv ----
    agg_kernel<<<(NN * 64 + 255) / 256, 256>>>((const uint2*)zh, ah);
    gemm_mma_kernel<2><<<dim3(NPAD / 128, 2), 256, SMEM_TOT_G>>>(ah, wtch,
                                                                 bcat, out_mu, out_lv, nullptr);
}

// round 16
// speedup vs baseline: 3.3903x; 1.1283x over previous
#include <cuda_runtime.h>
#include <cuda_fp16.h>
#include <cstdint>

#define NN 50000
#define NPAD 50048          // 391 * 128
#define NE 800000
#define DD 256
#define LAT 128
#define NBLK 196            // ceil(NN/256)
#define XCONV_BLKS 12500    // NN*64/256

// ---------------- scratch (static __device__ globals; no allocs) ----------
static __device__ int   g_is64;
static __device__ int   g_deg[NN];
static __device__ float g_dinv[NN];
static __device__ int   g_rowstart[NN + 1];
static __device__ int   g_pos[NN];
static __device__ int   g_bsum[256];
static __device__ int   g_boff[256];
static __device__ int   g_csrc[NE];
static __device__ float g_cnrm[NE];
static __device__ __align__(16) __half g_xh[(size_t)NN * DD];     // x as fp16
static __device__ __align__(16) __half g_zh[(size_t)NN * DD];     // z as fp16
static __device__ __align__(16) __half g_ah[(size_t)NPAD * DD];   // aggregated A (fp16)
static __device__ __align__(16) __half g_wt1h[DD * DD];           // W1^T [N,K] fp16
static __device__ __align__(16) __half g_wtch[DD * DD];           // [Wmu|Wlv]^T fp16
static __device__ float g_bcat[DD];

// ---------------- helpers ---------------------------------------------------
__device__ __forceinline__ uint32_t smem_u32(const void* p) {
    uint32_t a;
    asm("{ .reg .u64 t; cvta.to.shared.u64 t, %1; cvt.u32.u64 %0, t; }"
        : "=r"(a) : "l"(p));
    return a;
}

__device__ __forceinline__ int load_idx(const void* ei, int pos) {
    if (g_is64) return (int)((const long long*)ei)[pos];
    return ((const int*)ei)[pos];
}

// fma 8 halves (uint4) scaled by n into 8-float accumulator
__device__ __forceinline__ void h16_fma(float* acc, uint4 raw, float n) {
    const __half2* h2 = (const __half2*)&raw;
    #pragma unroll
    for (int q = 0; q < 4; q++) {
        float2 f = __half22float2(h2[q]);
        acc[2 * q + 0] += n * f.x;
        acc[2 * q + 1] += n * f.y;
    }
}

// ---------------- k1: zero deg + weight prep (fp16) + parallel detect ------
__global__ void prep_kernel(const void* __restrict__ ei,
                            const float* __restrict__ W1,
                            const float* __restrict__ Wmu,
                            const float* __restrict__ Wlv,
                            const float* __restrict__ bmu,
                            const float* __restrict__ blv) {
    int idx = blockIdx.x * 256 + threadIdx.x;      // 0..65535
    if (idx < NN) g_deg[idx] = 0;

    int n = idx >> 8, k = idx & 255;
    g_wt1h[idx] = __float2half(W1[k * DD + n]);
    float v2 = (n < LAT) ? Wmu[k * LAT + n] : Wlv[k * LAT + (n - LAT)];
    g_wtch[idx] = __float2half(v2);
    if (idx < DD) g_bcat[idx] = (idx < LAT) ? bmu[idx] : blv[idx - LAT];

    if (blockIdx.x == 0) {      // parallel int64-vs-int32 detection
        long long v = ((const long long*)ei)[threadIdx.x];
        int ok = (v >= 0 && v < NN) ? 1 : 0;
        int all = __syncthreads_and(ok);
        if (threadIdx.x == 0) g_is64 = all;
    }
}

// ---------------- k2: fused x->fp16 convert + degree count -----------------
__global__ void xconv_count_kernel(const float4* __restrict__ x4,
                                   const void* __restrict__ ei) {
    int b = blockIdx.x;
    if (b < XCONV_BLKS) {
        int idx = b * 256 + threadIdx.x;           // one float4 each
        float4 v = x4[idx];
        uint2 out;
        *(__half2*)&out.x = __floats2half2_rn(v.x, v.y);
        *(__half2*)&out.y = __floats2half2_rn(v.z, v.w);
        ((uint2*)g_xh)[idx] = out;
    } else {
        int e = (b - XCONV_BLKS) * 256 + threadIdx.x;
        if (e < NE) atomicAdd(&g_deg[load_idx(ei, NE + e)], 1);
    }
}

// ---- k3-k5: wide 3-kernel exclusive scan of g_deg + dinv -------------------
__global__ void scan1_kernel() {
    __shared__ int s[256];
    int t = threadIdx.x;
    int i = blockIdx.x * 256 + t;
    s[t] = (i < NN) ? g_deg[i] : 0;
    __syncthreads();
    for (int o = 128; o > 0; o >>= 1) {
        if (t < o) s[t] += s[t + o];
        __syncthreads();
    }
    if (t == 0) g_bsum[blockIdx.x] = s[0];
}

__global__ void scan2_kernel() {
    __shared__ int s[256];
    int t = threadIdx.x;
    int v = (t < NBLK) ? g_bsum[t] : 0;
    s[t] = v;
    __syncthreads();
    for (int o = 1; o < 256; o <<= 1) {
        int x = (t >= o) ? s[t - o] : 0;
        __syncthreads();
        s[t] += x;
        __syncthreads();
    }
    g_boff[t] = s[t] - v;
}

__global__ void scan3_kernel() {
    __shared__ int s[256];
    int t = threadIdx.x;
    int i = blockIdx.x * 256 + t;
    int v = (i < NN) ? g_deg[i] : 0;
    s[t] = v;
    __syncthreads();
    for (int o = 1; o < 256; o <<= 1) {
        int x = (t >= o) ? s[t - o] : 0;
        __syncthreads();
        s[t] += x;
        __syncthreads();
    }
    int excl = s[t] - v + g_boff[blockIdx.x];
    if (i < NN) {
        g_rowstart[i] = excl;
        g_pos[i] = excl;
        g_dinv[i] = rsqrtf((float)v + 1.0f);
        if (i == NN - 1) g_rowstart[NN] = excl + v;
    }
}

// ---------------- k6: CSR fill ----------------------------------------------
__global__ void csr_fill_kernel(const void* __restrict__ ei) {
    int e = blockIdx.x * blockDim.x + threadIdx.x;
    if (e < NE) {
        int s = load_idx(ei, e);
        int d = load_idx(ei, NE + e);
        int slot = atomicAdd(&g_pos[d], 1);
        g_csrc[slot] = s;
        g_cnrm[slot] = g_dinv[s] * g_dinv[d];
    }
}

// ---------------- CSR aggregation (fp16 gather, uint4 lanes) ----------------
// 32 threads per node (16B per thread); 8 nodes per 256-thread block.
__global__ void __launch_bounds__(256) agg_kernel(
        const uint4* __restrict__ feat, __half* __restrict__ out) {
    int gid = (blockIdx.x * blockDim.x + threadIdx.x) >> 5;
    int j   = threadIdx.x & 31;                    // uint4 lane
    if (gid >= NN) return;

    int beg = g_rowstart[gid];
    int end = g_rowstart[gid + 1];
    float d  = g_dinv[gid];
    float d2 = d * d;

    float acc[8] = {0, 0, 0, 0, 0, 0, 0, 0};
    h16_fma(acc, feat[(size_t)gid * 32 + j], d2);

    int e = beg;
    for (; e + 1 < end; e += 2) {
        int   s0 = g_csrc[e],     s1 = g_csrc[e + 1];
        float n0 = g_cnrm[e],     n1 = g_cnrm[e + 1];
        uint4 u0 = feat[(size_t)s0 * 32 + j];
        uint4 u1 = feat[(size_t)s1 * 32 + j];
        h16_fma(acc, u0, n0);
        h16_fma(acc, u1, n1);
    }
    if (e < end) {
        h16_fma(acc, feat[(size_t)g_csrc[e] * 32 + j], g_cnrm[e]);
    }

    uint4 o;
    __half2* oh = (__half2*)&o;
    #pragma unroll
    for (int q = 0; q < 4; q++)
        oh[q] = __floats2half2_rn(acc[2 * q], acc[2 * q + 1]);
    *(uint4*)(out + (size_t)gid * DD + 8 * j) = o;
}

// ---------------- mma.sync fp16 GEMM ---------------------------------------
// C[M,256] = A[M,256] @ B^T  (B stored [N,K], K-contiguous), fp16 in, fp32 acc.
// BM=128, BN=128, BK=32, 8 warps (warp tile 32x64), cp.async double buffer.
// EPI 1: z (fp16) = relu(C + bias). EPI 2: fp32 cols 0..127 -> mu, 128..255 -> lv.
#define SMEM_ARR   10240                 // 128 rows * 80 B
#define SMEM_STAGE (2 * SMEM_ARR)        // A, B
#define SMEM_TOT_G (2 * SMEM_STAGE)      // 40960 B

__device__ __forceinline__ void ldmx4(uint32_t* r, uint32_t addr) {
    asm volatile("ldmatrix.sync.aligned.m8n8.x4.shared.b16 {%0,%1,%2,%3}, [%4];"
                 : "=r"(r[0]), "=r"(r[1]), "=r"(r[2]), "=r"(r[3]) : "r"(addr));
}
__device__ __forceinline__ void mma16816h(float* c, const uint32_t* a,
                                          const uint32_t* b) {
    asm volatile(
        "mma.sync.aligned.m16n8k16.row.col.f32.f16.f16.f32 "
        "{%0,%1,%2,%3}, {%4,%5,%6,%7}, {%8,%9}, {%0,%1,%2,%3};"
        : "+f"(c[0]), "+f"(c[1]), "+f"(c[2]), "+f"(c[3])
        : "r"(a[0]), "r"(a[1]), "r"(a[2]), "r"(a[3]), "r"(b[0]), "r"(b[1]));
}

template <int EPI>
__global__ void __launch_bounds__(256) gemm_mma_kernel(
        const __half* __restrict__ A, const __half* __restrict__ B,
        const float* __restrict__ bias,
        float* __restrict__ out0, float* __restrict__ out1,
        __half* __restrict__ outh) {
    extern __shared__ char smem[];
    uint32_t sb = smem_u32(smem);
    int tid = threadIdx.x;
    int lane = tid & 31, w = tid >> 5;
    int warp_m = w & 3, warp_n = w >> 2;
    int row0 = blockIdx.x * 128;
    int col0 = blockIdx.y * 128;

    auto load_chunk = [&](int st, int c) {
        #pragma unroll
        for (int it = 0; it < 4; it++) {
            int i   = tid + it * 256;        // 0..1023
            int u   = i & 3;                 // 16B unit within 64B row-chunk
            int row = (i >> 2) & 127;
            int arr = i >> 9;                // 0:A 1:B
            const __half* base = arr ? B : A;
            int grow = arr ? (col0 + row) : (row0 + row);
            const void* src = base + (size_t)grow * DD + c * 32 + u * 8;
            uint32_t dst = sb + st * SMEM_STAGE + arr * SMEM_ARR + row * 80 + u * 16;
            asm volatile("cp.async.cg.shared.global [%0], [%1], 16;"
                         :: "r"(dst), "l"(src));
        }
        asm volatile("cp.async.commit_group;" ::: "memory");
    };

    float acc[2][8][4];
    #pragma unroll
    for (int i = 0; i < 2; i++)
        #pragma unroll
        for (int j = 0; j < 8; j++)
            #pragma unroll
            for (int q = 0; q < 4; q++) acc[i][j][q] = 0.0f;

    load_chunk(0, 0);
    asm volatile("cp.async.wait_group 0;" ::: "memory");
    __syncthreads();

    int ar  = 32 * warp_m + (lane & 15);
    int ac  = (lane >> 4) << 3;
    // B ldmatrix.x4 lane mapping: lanes 0-7 -> (n0-7,k0), 8-15 -> (n0-7,k8),
    // 16-23 -> (n8-15,k0), 24-31 -> (n8-15,k8)
    int br4 = 64 * warp_n + (lane & 7) + (((lane >> 4) & 1) << 3);
    int bc  = ((lane >> 3) & 1) << 3;

    for (int c = 0; c < 8; c++) {
        int st = c & 1;
        if (c < 7) load_chunk(st ^ 1, c + 1);

        uint32_t sA = sb + st * SMEM_STAGE;
        uint32_t sB = sA + SMEM_ARR;

        #pragma unroll
        for (int s = 0; s < 2; s++) {
            uint32_t af[2][4];
            #pragma unroll
            for (int i = 0; i < 2; i++) {
                uint32_t off = (uint32_t)(ar + 16 * i) * 80 + (ac + 16 * s) * 2;
                ldmx4(af[i], sA + off);
            }
            #pragma unroll
            for (int jp = 0; jp < 4; jp++) {      // n-pair: j = 2jp, 2jp+1
                uint32_t bf[4];
                uint32_t off = (uint32_t)(br4 + 16 * jp) * 80 + (bc + 16 * s) * 2;
                ldmx4(bf, sB + off);
                #pragma unroll
                for (int h = 0; h < 2; h++) {     // half of pair
                    int j = 2 * jp + h;
                    #pragma unroll
                    for (int i = 0; i < 2; i++)
                        mma16816h(acc[i][j], af[i], bf + 2 * h);
                }
            }
        }
        asm volatile("cp.async.wait_group 0;" ::: "memory");
        __syncthreads();
    }

    // ---- epilogue ----
    #pragma unroll
    for (int i = 0; i < 2; i++) {
        int r = row0 + 32 * warp_m + 16 * i + (lane >> 2);
        #pragma unroll
        for (int j = 0; j < 8; j++) {
            int cg = col0 + 64 * warp_n + 8 * j + ((lane & 3) << 1);
            float b0v = bias[cg], b1v = bias[cg + 1];
            float v0 = acc[i][j][0] + b0v, v1 = acc[i][j][1] + b1v;
            float v2 = acc[i][j][2] + b0v, v3 = acc[i][j][3] + b1v;
            if (EPI == 1) {
                v0 = fmaxf(v0, 0.0f); v1 = fmaxf(v1, 0.0f);
                v2 = fmaxf(v2, 0.0f); v3 = fmaxf(v3, 0.0f);
                if (r < NN)
                    *(__half2*)(outh + (size_t)r * DD + cg) = __floats2half2_rn(v0, v1);
                if (r + 8 < NN)
                    *(__half2*)(outh + (size_t)(r + 8) * DD + cg) = __floats2half2_rn(v2, v3);
            } else {
                float* o  = (cg < LAT) ? out0 + (size_t)r * LAT + cg
                                       : out1 + (size_t)r * LAT + (cg - LAT);
                float* o8 = (cg < LAT) ? out0 + (size_t)(r + 8) * LAT + cg
                                       : out1 + (size_t)(r + 8) * LAT + (cg - LAT);
                if (r < NN)     *(float2*)o  = make_float2(v0, v1);
                if (r + 8 < NN) *(float2*)o8 = make_float2(v2, v3);
            }
        }
    }
}

// ---------------- launch ---------------------------------------------------
extern "C" void kernel_launch(void* const* d_in, const int* in_sizes, int n_in,
                              void* d_out, int out_size) {
    const float* x    = (const float*)d_in[0];
    const void*  ei   = d_in[1];
    const float* W1   = (const float*)d_in[2];
    const float* b1   = (const float*)d_in[3];
    const float* Wmu  = (const float*)d_in[4];
    const float* bmu  = (const float*)d_in[5];
    const float* Wlv  = (const float*)d_in[6];
    const float* blv  = (const float*)d_in[7];
    float* out_mu = (float*)d_out;
    float* out_lv = (float*)d_out + (size_t)NN * LAT;

    __half *xh = nullptr, *zh = nullptr, *ah = nullptr;
    __half *wt1h = nullptr, *wtch = nullptr;
    float* bcat = nullptr;
    cudaGetSymbolAddress((void**)&xh,   g_xh);
    cudaGetSymbolAddress((void**)&zh,   g_zh);
    cudaGetSymbolAddress((void**)&ah,   g_ah);
    cudaGetSymbolAddress((void**)&wt1h, g_wt1h);
    cudaGetSymbolAddress((void**)&wtch, g_wtch);
    cudaGetSymbolAddress((void**)&bcat, g_bcat);
    (void)n_in; (void)in_sizes; (void)out_size;

    cudaFuncSetAttribute(gemm_mma_kernel<1>,
                         cudaFuncAttributeMaxDynamicSharedMemorySize, SMEM_TOT_G);
    cudaFuncSetAttribute(gemm_mma_kernel<2>,
                         cudaFuncAttributeMaxDynamicSharedMemorySize, SMEM_TOT_G);

    // ---- graph prep (6 kernels) ----
    prep_kernel<<<256, 256>>>(ei, W1, Wmu, Wlv, bmu, blv);
    xconv_count_kernel<<<XCONV_BLKS + (NE + 255) / 256, 256>>>((const float4*)x, ei);
    scan1_kernel<<<NBLK, 256>>>();
    scan2_kernel<<<1, 256>>>();
    scan3_kernel<<<NBLK, 256>>>();
    csr_fill_kernel<<<(NE + 255) / 256, 256>>>(ei);

    // ---- layer 1: agg(x fp16) -> A ; GEMM -> z (fp16) ----
    agg_kernel<<<(NN * 32 + 255) / 256, 256>>>((const uint4*)xh, ah);
    gemm_mma_kernel<1><<<dim3(NPAD / 128, 2), 256, SMEM_TOT_G>>>(ah, wt1h,
                                                                 b1, nullptr, nullptr, zh);

    // ---- layers 2/3: agg(z fp16) -> A ; fused N=256 GEMM -> mu, lv ----
    agg_kernel<<<(NN * 32 + 255) / 256, 256>>>((const uint4*)zh, ah);
    gemm_mma_kernel<2><<<dim3(NPAD / 128, 2), 256, SMEM_TOT_G>>>(ah, wtch,
                                                                 bcat, out_mu, out_lv, nullptr);
}

// round 17
// speedup vs baseline: 3.5707x; 1.0532x over previous
#include <cuda_runtime.h>
#include <cuda_fp16.h>
#include <cstdint>

#define NN 50000
#define NPAD 50048          // 391 * 128
#define NE 800000
#define DD 256
#define LAT 128
#define NBLK 196            // ceil(NN/256)
#define XCONV_BLKS 12500    // NN*64/256

// ---------------- scratch (static __device__ globals; no allocs) ----------
static __device__ int   g_is64;
static __device__ int   g_deg[NN];
static __device__ float g_dinv[NN];
static __device__ int   g_rowstart[NN + 1];
static __device__ int   g_pos[NN];
static __device__ int   g_bsum[256];
static __device__ __align__(8) int2 g_edge[NE];   // {src, norm bits} packed
static __device__ __align__(16) __half g_xh[(size_t)NN * DD];     // x as fp16
static __device__ __align__(16) __half g_zh[(size_t)NN * DD];     // z as fp16
static __device__ __align__(16) __half g_ah[(size_t)NPAD * DD];   // aggregated A (fp16)
static __device__ __align__(16) __half g_wt1h[DD * DD];           // W1^T [N,K] fp16
static __device__ __align__(16) __half g_wtch[DD * DD];           // [Wmu|Wlv]^T fp16
static __device__ float g_bcat[DD];

// ---------------- helpers ---------------------------------------------------
__device__ __forceinline__ uint32_t smem_u32(const void* p) {
    uint32_t a;
    asm("{ .reg .u64 t; cvta.to.shared.u64 t, %1; cvt.u32.u64 %0, t; }"
        : "=r"(a) : "l"(p));
    return a;
}

__device__ __forceinline__ int load_idx(const void* ei, int pos) {
    if (g_is64) return (int)((const long long*)ei)[pos];
    return ((const int*)ei)[pos];
}

// fma 8 halves (uint4) scaled by n into 8-float accumulator
__device__ __forceinline__ void h16_fma(float* acc, uint4 raw, float n) {
    const __half2* h2 = (const __half2*)&raw;
    #pragma unroll
    for (int q = 0; q < 4; q++) {
        float2 f = __half22float2(h2[q]);
        acc[2 * q + 0] += n * f.x;
        acc[2 * q + 1] += n * f.y;
    }
}

// ---------------- k1: zero deg + weight prep (fp16) + parallel detect ------
__global__ void prep_kernel(const void* __restrict__ ei,
                            const float* __restrict__ W1,
                            const float* __restrict__ Wmu,
                            const float* __restrict__ Wlv,
                            const float* __restrict__ bmu,
                            const float* __restrict__ blv) {
    int idx = blockIdx.x * 256 + threadIdx.x;      // 0..65535
    if (idx < NN) g_deg[idx] = 0;

    int n = idx >> 8, k = idx & 255;
    g_wt1h[idx] = __float2half(W1[k * DD + n]);
    float v2 = (n < LAT) ? Wmu[k * LAT + n] : Wlv[k * LAT + (n - LAT)];
    g_wtch[idx] = __float2half(v2);
    if (idx < DD) g_bcat[idx] = (idx < LAT) ? bmu[idx] : blv[idx - LAT];

    if (blockIdx.x == 0) {      // parallel int64-vs-int32 detection
        long long v = ((const long long*)ei)[threadIdx.x];
        int ok = (v >= 0 && v < NN) ? 1 : 0;
        int all = __syncthreads_and(ok);
        if (threadIdx.x == 0) g_is64 = all;
    }
}

// ---------------- k2: fused x->fp16 convert + degree count -----------------
__global__ void xconv_count_kernel(const float4* __restrict__ x4,
                                   const void* __restrict__ ei) {
    int b = blockIdx.x;
    if (b < XCONV_BLKS) {
        int idx = b * 256 + threadIdx.x;           // one float4 each
        float4 v = x4[idx];
        uint2 out;
        *(__half2*)&out.x = __floats2half2_rn(v.x, v.y);
        *(__half2*)&out.y = __floats2half2_rn(v.z, v.w);
        ((uint2*)g_xh)[idx] = out;
    } else {
        int e = (b - XCONV_BLKS) * 256 + threadIdx.x;
        if (e < NE) atomicAdd(&g_deg[load_idx(ei, NE + e)], 1);
    }
}

// ---- k3-k4: 2-kernel exclusive scan of g_deg + dinv ------------------------
__global__ void scan1_kernel() {
    __shared__ int s[256];
    int t = threadIdx.x;
    int i = blockIdx.x * 256 + t;
    s[t] = (i < NN) ? g_deg[i] : 0;
    __syncthreads();
    for (int o = 128; o > 0; o >>= 1) {
        if (t < o) s[t] += s[t + o];
        __syncthreads();
    }
    if (t == 0) g_bsum[blockIdx.x] = s[0];
}

// per-element scan; block offset computed in-block from g_bsum (196 values)
__global__ void scan3_kernel() {
    __shared__ int s[256];
    __shared__ int sboff;
    int t = threadIdx.x;

    // boff = sum of g_bsum[0..blockIdx) via block reduction
    int part = (t < blockIdx.x) ? g_bsum[t] : 0;   // blockIdx.x <= 195 < 256
    s[t] = part;
    __syncthreads();
    for (int o = 128; o > 0; o >>= 1) {
        if (t < o) s[t] += s[t + o];
        __syncthreads();
    }
    if (t == 0) sboff = s[0];
    __syncthreads();
    int boff = sboff;
    __syncthreads();

    int i = blockIdx.x * 256 + t;
    int v = (i < NN) ? g_deg[i] : 0;
    s[t] = v;
    __syncthreads();
    for (int o = 1; o < 256; o <<= 1) {
        int x = (t >= o) ? s[t - o] : 0;
        __syncthreads();
        s[t] += x;
        __syncthreads();
    }
    int excl = s[t] - v + boff;
    if (i < NN) {
        g_rowstart[i] = excl;
        g_pos[i] = excl;
        g_dinv[i] = rsqrtf((float)v + 1.0f);
        if (i == NN - 1) g_rowstart[NN] = excl + v;
    }
}

// ---------------- k5: CSR fill (packed 8B records) --------------------------
__global__ void csr_fill_kernel(const void* __restrict__ ei) {
    int e = blockIdx.x * blockDim.x + threadIdx.x;
    if (e < NE) {
        int s = load_idx(ei, e);
        int d = load_idx(ei, NE + e);
        int slot = atomicAdd(&g_pos[d], 1);
        g_edge[slot] = make_int2(s, __float_as_int(g_dinv[s] * g_dinv[d]));
    }
}

// ---------------- CSR aggregation (fp16 gather, uint4 lanes) ----------------
// 32 threads per node (16B per thread); 8 nodes per 256-thread block.
__global__ void __launch_bounds__(256) agg_kernel(
        const uint4* __restrict__ feat, __half* __restrict__ out) {
    int gid = (blockIdx.x * blockDim.x + threadIdx.x) >> 5;
    int j   = threadIdx.x & 31;                    // uint4 lane
    if (gid >= NN) return;

    int beg = g_rowstart[gid];
    int end = g_rowstart[gid + 1];
    float d  = g_dinv[gid];
    float d2 = d * d;

    float acc[8] = {0, 0, 0, 0, 0, 0, 0, 0};
    h16_fma(acc, feat[(size_t)gid * 32 + j], d2);

    int e = beg;
    for (; e + 1 < end; e += 2) {
        int2 ed0 = g_edge[e];
        int2 ed1 = g_edge[e + 1];
        uint4 u0 = feat[(size_t)ed0.x * 32 + j];
        uint4 u1 = feat[(size_t)ed1.x * 32 + j];
        h16_fma(acc, u0, __int_as_float(ed0.y));
        h16_fma(acc, u1, __int_as_float(ed1.y));
    }
    if (e < end) {
        int2 ed0 = g_edge[e];
        h16_fma(acc, feat[(size_t)ed0.x * 32 + j], __int_as_float(ed0.y));
    }

    uint4 o;
    __half2* oh = (__half2*)&o;
    #pragma unroll
    for (int q = 0; q < 4; q++)
        oh[q] = __floats2half2_rn(acc[2 * q], acc[2 * q + 1]);
    *(uint4*)(out + (size_t)gid * DD + 8 * j) = o;
}

// ---------------- mma.sync fp16 GEMM ---------------------------------------
// C[M,256] = A[M,256] @ B^T  (B stored [N,K], K-contiguous), fp16 in, fp32 acc.
// BM=128, BN=128, BK=32, 8 warps (warp tile 32x64), cp.async double buffer.
// EPI 1: z (fp16) = relu(C + bias). EPI 2: fp32 cols 0..127 -> mu, 128..255 -> lv.
#define SMEM_ARR   10240                 // 128 rows * 80 B
#define SMEM_STAGE (2 * SMEM_ARR)        // A, B
#define SMEM_TOT_G (2 * SMEM_STAGE)      // 40960 B

__device__ __forceinline__ void ldmx4(uint32_t* r, uint32_t addr) {
    asm volatile("ldmatrix.sync.aligned.m8n8.x4.shared.b16 {%0,%1,%2,%3}, [%4];"
                 : "=r"(r[0]), "=r"(r[1]), "=r"(r[2]), "=r"(r[3]) : "r"(addr));
}
__device__ __forceinline__ void mma16816h(float* c, const uint32_t* a,
                                          const uint32_t* b) {
    asm volatile(
        "mma.sync.aligned.m16n8k16.row.col.f32.f16.f16.f32 "
        "{%0,%1,%2,%3}, {%4,%5,%6,%7}, {%8,%9}, {%0,%1,%2,%3};"
        : "+f"(c[0]), "+f"(c[1]), "+f"(c[2]), "+f"(c[3])
        : "r"(a[0]), "r"(a[1]), "r"(a[2]), "r"(a[3]), "r"(b[0]), "r"(b[1]));
}

template <int EPI>
__global__ void __launch_bounds__(256) gemm_mma_kernel(
        const __half* __restrict__ A, const __half* __restrict__ B,
        const float* __restrict__ bias,
        float* __restrict__ out0, float* __restrict__ out1,
        __half* __restrict__ outh) {
    extern __shared__ char smem[];
    uint32_t sb = smem_u32(smem);
    int tid = threadIdx.x;
    int lane = tid & 31, w = tid >> 5;
    int warp_m = w & 3, warp_n = w >> 2;
    int row0 = blockIdx.x * 128;
    int col0 = blockIdx.y * 128;

    auto load_chunk = [&](int st, int c) {
        #pragma unroll
        for (int it = 0; it < 4; it++) {
            int i   = tid + it * 256;        // 0..1023
            int u   = i & 3;                 // 16B unit within 64B row-chunk
            int row = (i >> 2) & 127;
            int arr = i >> 9;                // 0:A 1:B
            const __half* base = arr ? B : A;
            int grow = arr ? (col0 + row) : (row0 + row);
            const void* src = base + (size_t)grow * DD + c * 32 + u * 8;
            uint32_t dst = sb + st * SMEM_STAGE + arr * SMEM_ARR + row * 80 + u * 16;
            asm volatile("cp.async.cg.shared.global [%0], [%1], 16;"
                         :: "r"(dst), "l"(src));
        }
        asm volatile("cp.async.commit_group;" ::: "memory");
    };

    float acc[2][8][4];
    #pragma unroll
    for (int i = 0; i < 2; i++)
        #pragma unroll
        for (int j = 0; j < 8; j++)
            #pragma unroll
            for (int q = 0; q < 4; q++) acc[i][j][q] = 0.0f;

    load_chunk(0, 0);
    asm volatile("cp.async.wait_group 0;" ::: "memory");
    __syncthreads();

    int ar  = 32 * warp_m + (lane & 15);
    int ac  = (lane >> 4) << 3;
    // B ldmatrix.x4 lane mapping: lanes 0-7 -> (n0-7,k0), 8-15 -> (n0-7,k8),
    // 16-23 -> (n8-15,k0), 24-31 -> (n8-15,k8)
    int br4 = 64 * warp_n + (lane & 7) + (((lane >> 4) & 1) << 3);
    int bc  = ((lane >> 3) & 1) << 3;

    for (int c = 0; c < 8; c++) {
        int st = c & 1;
        if (c < 7) load_chunk(st ^ 1, c + 1);

        uint32_t sA = sb + st * SMEM_STAGE;
        uint32_t sB = sA + SMEM_ARR;

        #pragma unroll
        for (int s = 0; s < 2; s++) {
            uint32_t af[2][4];
            #pragma unroll
            for (int i = 0; i < 2; i++) {
                uint32_t off = (uint32_t)(ar + 16 * i) * 80 + (ac + 16 * s) * 2;
                ldmx4(af[i], sA + off);
            }
            #pragma unroll
            for (int jp = 0; jp < 4; jp++) {      // n-pair: j = 2jp, 2jp+1
                uint32_t bf[4];
                uint32_t off = (uint32_t)(br4 + 16 * jp) * 80 + (bc + 16 * s) * 2;
                ldmx4(bf, sB + off);
                #pragma unroll
                for (int h = 0; h < 2; h++) {     // half of pair
                    int j = 2 * jp + h;
                    #pragma unroll
                    for (int i = 0; i < 2; i++)
                        mma16816h(acc[i][j], af[i], bf + 2 * h);
                }
            }
        }
        asm volatile("cp.async.wait_group 0;" ::: "memory");
        __syncthreads();
    }

    // ---- epilogue ----
    #pragma unroll
    for (int i = 0; i < 2; i++) {
        int r = row0 + 32 * warp_m + 16 * i + (lane >> 2);
        #pragma unroll
        for (int j = 0; j < 8; j++) {
            int cg = col0 + 64 * warp_n + 8 * j + ((lane & 3) << 1);
            float b0v = bias[cg], b1v = bias[cg + 1];
            float v0 = acc[i][j][0] + b0v, v1 = acc[i][j][1] + b1v;
            float v2 = acc[i][j][2] + b0v, v3 = acc[i][j][3] + b1v;
            if (EPI == 1) {
                v0 = fmaxf(v0, 0.0f); v1 = fmaxf(v1, 0.0f);
                v2 = fmaxf(v2, 0.0f); v3 = fmaxf(v3, 0.0f);
                if (r < NN)
                    *(__half2*)(outh + (size_t)r * DD + cg) = __floats2half2_rn(v0, v1);
                if (r + 8 < NN)
                    *(__half2*)(outh + (size_t)(r + 8) * DD + cg) = __floats2half2_rn(v2, v3);
            } else {
                float* o  = (cg < LAT) ? out0 + (size_t)r * LAT + cg
                                       : out1 + (size_t)r * LAT + (cg - LAT);
                float* o8 = (cg < LAT) ? out0 + (size_t)(r + 8) * LAT + cg
                                       : out1 + (size_t)(r + 8) * LAT + (cg - LAT);
                if (r < NN)     *(float2*)o  = make_float2(v0, v1);
                if (r + 8 < NN) *(float2*)o8 = make_float2(v2, v3);
            }
        }
    }
}

// ---------------- launch ---------------------------------------------------
extern "C" void kernel_launch(void* const* d_in, const int* in_sizes, int n_in,
                              void* d_out, int out_size) {
    const float* x    = (const float*)d_in[0];
    const void*  ei   = d_in[1];
    const float* W1   = (const float*)d_in[2];
    const float* b1   = (const float*)d_in[3];
    const float* Wmu  = (const float*)d_in[4];
    const float* bmu  = (const float*)d_in[5];
    const float* Wlv  = (const float*)d_in[6];
    const float* blv  = (const float*)d_in[7];
    float* out_mu = (float*)d_out;
    float* out_lv = (float*)d_out + (size_t)NN * LAT;

    __half *xh = nullptr, *zh = nullptr, *ah = nullptr;
    __half *wt1h = nullptr, *wtch = nullptr;
    float* bcat = nullptr;
    cudaGetSymbolAddress((void**)&xh,   g_xh);
    cudaGetSymbolAddress((void**)&zh,   g_zh);
    cudaGetSymbolAddress((void**)&ah,   g_ah);
    cudaGetSymbolAddress((void**)&wt1h, g_wt1h);
    cudaGetSymbolAddress((void**)&wtch, g_wtch);
    cudaGetSymbolAddress((void**)&bcat, g_bcat);
    (void)n_in; (void)in_sizes; (void)out_size;

    cudaFuncSetAttribute(gemm_mma_kernel<1>,
                         cudaFuncAttributeMaxDynamicSharedMemorySize, SMEM_TOT_G);
    cudaFuncSetAttribute(gemm_mma_kernel<2>,
                         cudaFuncAttributeMaxDynamicSharedMemorySize, SMEM_TOT_G);

    // ---- graph prep (5 kernels) ----
    prep_kernel<<<256, 256>>>(ei, W1, Wmu, Wlv, bmu, blv);
    xconv_count_kernel<<<XCONV_BLKS + (NE + 255) / 256, 256>>>((const float4*)x, ei);
    scan1_kernel<<<NBLK, 256>>>();
    scan3_kernel<<<NBLK, 256>>>();
    csr_fill_kernel<<<(NE + 255) / 256, 256>>>(ei);

    // ---- layer 1: agg(x fp16) -> A ; GEMM -> z (fp16) ----
    agg_kernel<<<(NN * 32 + 255) / 256, 256>>>((const uint4*)xh, ah);
    gemm_mma_kernel<1><<<dim3(NPAD / 128, 2), 256, SMEM_TOT_G>>>(ah, wt1h,
                                                                 b1, nullptr, nullptr, zh);

    // ---- layers 2/3: agg(z fp16) -> A ; fused N=256 GEMM -> mu, lv ----
    agg_kernel<<<(NN * 32 + 255) / 256, 256>>>((const uint4*)zh, ah);
    gemm_mma_kernel<2><<<dim3(NPAD / 128, 2), 256, SMEM_TOT_G>>>(ah, wtch,
                                                                 bcat, out_mu, out_lv, nullptr);
}